// round 1
// baseline (speedup 1.0000x reference)
#include <cuda_runtime.h>
#include <math.h>

#define H 256
#define FIN 58
#define N_MAX 100000

// ---------------- scratch (device globals; no allocation allowed) ------------
__device__ float g_R   [(size_t)N_MAX * H];      // current features (v)
__device__ float g_QK  [(size_t)N_MAX * 2 * H];  // [q | k] per row
__device__ float g_Rn  [(size_t)N_MAX * H];      // conv output (attn + gcn)
__device__ float g_deg [N_MAX];
__device__ float g_dinv[N_MAX];
__device__ float g_invden[N_MAX];
__device__ float g_kv  [H * H];                  // k^T v (unnormalized)
__device__ float g_stats[2 + 2 * H];             // [q2, k2, ksum[256], vsum[256]]
__device__ float g_s[1];                         // 1/(||q||*||k||)
__device__ float g_Wqk[H * 2 * H];
__device__ float g_bqk[2 * H];

// ---------------- tiny utility kernels ---------------------------------------
__global__ void zero_k(float* p, int n) {
    int i = blockIdx.x * blockDim.x + threadIdx.x;
    if (i < n) p[i] = 0.f;
}

__global__ void deg_acc(const int* __restrict__ col, int E) {
    int i = blockIdx.x * blockDim.x + threadIdx.x;
    if (i < E) atomicAdd(&g_deg[col[i]], 1.0f);
}

__global__ void invsqrt_k(int n) {
    int i = blockIdx.x * blockDim.x + threadIdx.x;
    if (i < n) {
        float d = g_deg[i];
        g_dinv[i] = (d > 0.f) ? 1.0f / sqrtf(d) : 0.f;
    }
}

__global__ void build_wqk(const float* __restrict__ Wq, const float* __restrict__ bq,
                          const float* __restrict__ Wk, const float* __restrict__ bk) {
    int idx = blockIdx.x * blockDim.x + threadIdx.x;
    if (idx < H * 2 * H) {
        int r = idx >> 9, c = idx & 511;
        g_Wqk[idx] = (c < H) ? Wq[r * H + c] : Wk[r * H + (c - H)];
    }
    if (idx < 2 * H) g_bqk[idx] = (idx < H) ? bq[idx] : bk[idx - H];
}

// ---------------- generic SGEMM: C[MxDn] = A[MxK] @ B[KxDn] -------------------
// EPI 0: +bias   EPI 1: relu(+bias)   EPI 2: (acc*s + vsum[c]) * invden[r]
template <int EPI>
__global__ __launch_bounds__(256) void sgemm(
    const float* __restrict__ A, int lda,
    const float* __restrict__ B, int ldb,
    const float* __restrict__ bias,
    float* __restrict__ C, int ldc,
    int M, int K,
    const float* __restrict__ vsum,
    const float* __restrict__ invden)
{
    __shared__ float As[8][128];
    __shared__ float Bs[8][128];
    const int tid  = threadIdx.x;
    const int row0 = blockIdx.y * 128, col0 = blockIdx.x * 128;
    const int tr = tid >> 4, tc = tid & 15;
    const int ar = tid >> 1, as_ = (tid & 1) * 4;
    const int bkr = tid >> 5, bc = (tid & 31) * 4;

    float acc[8][8] = {};
    const int ksteps = (K + 7) / 8;
    for (int kt = 0; kt < ksteps; kt++) {
        int k0 = kt * 8;
        {   // A tile (guarded scalar loads, stored transposed)
            int r = row0 + ar;
            #pragma unroll
            for (int j = 0; j < 4; j++) {
                int k = k0 + as_ + j;
                As[as_ + j][ar] = (r < M && k < K) ? A[(size_t)r * lda + k] : 0.f;
            }
        }
        {   // B tile (vectorized)
            int k = k0 + bkr;
            float4 v = make_float4(0.f, 0.f, 0.f, 0.f);
            if (k < K) v = *(const float4*)&B[(size_t)k * ldb + col0 + bc];
            *(float4*)&Bs[bkr][bc] = v;
        }
        __syncthreads();
        #pragma unroll
        for (int kk = 0; kk < 8; kk++) {
            float a[8], b[8];
            *(float4*)&a[0] = *(const float4*)&As[kk][tr * 8];
            *(float4*)&a[4] = *(const float4*)&As[kk][tr * 8 + 4];
            *(float4*)&b[0] = *(const float4*)&Bs[kk][tc * 8];
            *(float4*)&b[4] = *(const float4*)&Bs[kk][tc * 8 + 4];
            #pragma unroll
            for (int i = 0; i < 8; i++)
                #pragma unroll
                for (int j = 0; j < 8; j++)
                    acc[i][j] += a[i] * b[j];
        }
        __syncthreads();
    }

    float bb[8];
    float s = 0.f;
    if (EPI == 0 || EPI == 1) {
        #pragma unroll
        for (int j = 0; j < 8; j++) bb[j] = bias[col0 + tc * 8 + j];
    }
    if (EPI == 2) {
        s = g_s[0];
        #pragma unroll
        for (int j = 0; j < 8; j++) bb[j] = vsum[col0 + tc * 8 + j];
    }
    #pragma unroll
    for (int i = 0; i < 8; i++) {
        int r = row0 + tr * 8 + i;
        if (r >= M) continue;
        float id = (EPI == 2) ? invden[r] : 0.f;
        #pragma unroll
        for (int j = 0; j < 8; j += 4) {
            float4 v;
            float* pv = &v.x;
            #pragma unroll
            for (int q = 0; q < 4; q++) {
                float val = acc[i][j + q];
                if (EPI == 0) val += bb[j + q];
                if (EPI == 1) val = fmaxf(val + bb[j + q], 0.f);
                if (EPI == 2) val = (val * s + bb[j + q]) * id;
                pv[q] = val;
            }
            *(float4*)&C[(size_t)r * ldc + col0 + tc * 8 + j] = v;
        }
    }
}

// ---------------- kv = k^T @ v (split-N, atomic accumulate) -------------------
__global__ __launch_bounds__(256) void kv_gemm(int M) {
    __shared__ float Ks[8][64];
    __shared__ float Rs[8][64];
    const int m0 = blockIdx.x * 64, d0 = blockIdx.y * 64;
    const int n0 = blockIdx.z * 1024;
    const int tid = threadIdx.x;
    const int ls = tid >> 5, lm = (tid & 31) * 2;
    const int tm = tid >> 4, tn = tid & 15;
    float acc[4][4] = {};
    int nend = n0 + 1024; if (nend > M) nend = M;
    for (int n = n0; n < nend; n += 8) {
        int rr = n + ls;
        float2 kvl = make_float2(0.f, 0.f), rv = make_float2(0.f, 0.f);
        if (rr < M) {
            kvl = *(const float2*)&g_QK[(size_t)rr * 512 + 256 + m0 + lm];
            rv  = *(const float2*)&g_R [(size_t)rr * 256 + d0 + lm];
        }
        Ks[ls][lm] = kvl.x; Ks[ls][lm + 1] = kvl.y;
        Rs[ls][lm] = rv.x;  Rs[ls][lm + 1] = rv.y;
        __syncthreads();
        #pragma unroll
        for (int kk = 0; kk < 8; kk++) {
            float a[4], b[4];
            *(float4*)a = *(const float4*)&Ks[kk][tm * 4];
            *(float4*)b = *(const float4*)&Rs[kk][tn * 4];
            #pragma unroll
            for (int i = 0; i < 4; i++)
                #pragma unroll
                for (int j = 0; j < 4; j++)
                    acc[i][j] += a[i] * b[j];
        }
        __syncthreads();
    }
    #pragma unroll
    for (int i = 0; i < 4; i++)
        #pragma unroll
        for (int j = 0; j < 4; j++)
            atomicAdd(&g_kv[(m0 + tm * 4 + i) * 256 + d0 + tn * 4 + j], acc[i][j]);
}

// ---------------- stats: ||q||^2, ||k||^2, colsum(k), colsum(v) ---------------
__global__ __launch_bounds__(256) void reduce_stats(int M) {
    int t = threadIdx.x;
    int r0 = blockIdx.x * 128;
    int rend = r0 + 128; if (rend > M) rend = M;
    float q2 = 0.f, k2 = 0.f, ks = 0.f, vs = 0.f;
    for (int r = r0; r < rend; r++) {
        float qv  = g_QK[(size_t)r * 512 + t];
        float kvv = g_QK[(size_t)r * 512 + 256 + t];
        float vv  = g_R [(size_t)r * 256 + t];
        q2 += qv * qv; k2 += kvv * kvv; ks += kvv; vs += vv;
    }
    atomicAdd(&g_stats[2 + t], ks);
    atomicAdd(&g_stats[2 + 256 + t], vs);
    __shared__ float sq[256], sk[256];
    sq[t] = q2; sk[t] = k2; __syncthreads();
    for (int o = 128; o > 0; o >>= 1) {
        if (t < o) { sq[t] += sq[t + o]; sk[t] += sk[t + o]; }
        __syncthreads();
    }
    if (t == 0) { atomicAdd(&g_stats[0], sq[0]); atomicAdd(&g_stats[1], sk[0]); }
}

__global__ void finalize_s() {
    g_s[0] = rsqrtf(g_stats[0]) * rsqrtf(g_stats[1]);
}

// ---------------- per-row denominator: 1 / (s * (q . ksum) + N) ---------------
__global__ void den_kernel(int M, float fN) {
    int gw = (blockIdx.x * blockDim.x + threadIdx.x) >> 5;
    int l = threadIdx.x & 31;
    if (gw >= M) return;
    const float* q = &g_QK[(size_t)gw * 512];
    float sum = 0.f;
    #pragma unroll
    for (int j = 0; j < 8; j++) {
        int idx = j * 32 + l;
        sum += q[idx] * g_stats[2 + idx];
    }
    #pragma unroll
    for (int o = 16; o > 0; o >>= 1) sum += __shfl_xor_sync(0xffffffffu, sum, o);
    if (l == 0) g_invden[gw] = 1.0f / (g_s[0] * sum + fN);
}

// ---------------- GCN scatter: Rn[c] += dinv[r]*dinv[c] * R[r] ----------------
// One warp per edge, 128 dims per pass (keeps gather+scatter halves L2-resident)
__global__ void gcn_edges(const int* __restrict__ erow, const int* __restrict__ ecol,
                          int E, int dimoff) {
    long long t = (long long)blockIdx.x * blockDim.x + threadIdx.x;
    long long gw = t >> 5;
    if (gw >= E) return;
    int l = threadIdx.x & 31;
    int r = erow[gw], c = ecol[gw];
    float wt = g_dinv[r] * g_dinv[c];
    float4 v = *(const float4*)&g_R[(size_t)r * 256 + dimoff + l * 4];
    float* dst = &g_Rn[(size_t)c * 256 + dimoff + l * 4];
#if __CUDA_ARCH__ >= 900
    asm volatile("red.global.add.v4.f32 [%0], {%1,%2,%3,%4};"
                 :: "l"(dst), "f"(v.x * wt), "f"(v.y * wt), "f"(v.z * wt), "f"(v.w * wt)
                 : "memory");
#else
    atomicAdd(dst + 0, v.x * wt);
    atomicAdd(dst + 1, v.y * wt);
    atomicAdd(dst + 2, v.z * wt);
    atomicAdd(dst + 3, v.w * wt);
#endif
}

// ---------------- blend + LayerNorm + readout accumulate ----------------------
__global__ void blend_ln(const float* __restrict__ alpha_p,
                         const float* __restrict__ gamma, const float* __restrict__ beta,
                         const float* __restrict__ Wr, const float* __restrict__ br,
                         const float* __restrict__ wgt, int sidx,
                         float* __restrict__ out, int M)
{
    int gw = (blockIdx.x * blockDim.x + threadIdx.x) >> 5;
    int l = threadIdx.x & 31;
    if (gw >= M) return;
    float al = alpha_p[0];
    size_t base = (size_t)gw * 256;
    float h[8]; float sum = 0.f, sq = 0.f;
    #pragma unroll
    for (int j = 0; j < 8; j++) {
        int idx = j * 32 + l;
        float v = al * g_Rn[base + idx] + (1.f - al) * g_R[base + idx];
        h[j] = v; sum += v; sq += v * v;
    }
    #pragma unroll
    for (int o = 16; o > 0; o >>= 1) {
        sum += __shfl_xor_sync(0xffffffffu, sum, o);
        sq  += __shfl_xor_sync(0xffffffffu, sq, o);
    }
    float mu  = sum * (1.f / 256.f);
    float var = sq * (1.f / 256.f) - mu * mu;
    float rstd = rsqrtf(var + 1e-5f);
    const float* wr = Wr + sidx * 256;
    float dot = 0.f;
    #pragma unroll
    for (int j = 0; j < 8; j++) {
        int idx = j * 32 + l;
        float y = (h[j] - mu) * rstd * gamma[idx] + beta[idx];
        g_R[base + idx] = y;
        dot += y * wr[idx];
    }
    #pragma unroll
    for (int o = 16; o > 0; o >>= 1) dot += __shfl_xor_sync(0xffffffffu, dot, o);
    if (l == 0) out[gw] += wgt[sidx] * (dot + br[sidx]);
}

// ---------------- stage-0 readout (overwrites poisoned d_out) -----------------
__global__ void readout0(const float* __restrict__ Wr, const float* __restrict__ br,
                         const float* __restrict__ wgt, float* __restrict__ out, int M)
{
    int gw = (blockIdx.x * blockDim.x + threadIdx.x) >> 5;
    int l = threadIdx.x & 31;
    if (gw >= M) return;
    float dot = 0.f;
    #pragma unroll
    for (int j = 0; j < 8; j++) {
        int idx = j * 32 + l;
        dot += g_R[(size_t)gw * 256 + idx] * Wr[idx];
    }
    #pragma unroll
    for (int o = 16; o > 0; o >>= 1) dot += __shfl_xor_sync(0xffffffffu, dot, o);
    if (l == 0) out[gw] = wgt[0] * (dot + br[0]);
}

// ---------------- host orchestration ------------------------------------------
extern "C" void kernel_launch(void* const* d_in, const int* in_sizes, int n_in,
                              void* d_out, int out_size)
{
    const float* x     = (const float*)d_in[0];
    const int*   ei    = (const int*)  d_in[1];
    const float* W1    = (const float*)d_in[2];
    const float* b1    = (const float*)d_in[3];
    const float* Wq    = (const float*)d_in[4];
    const float* bq    = (const float*)d_in[5];
    const float* Wk    = (const float*)d_in[6];
    const float* bk    = (const float*)d_in[7];
    const float* gamma = (const float*)d_in[8];
    const float* beta  = (const float*)d_in[9];
    const float* alpha = (const float*)d_in[10];
    const float* Wr    = (const float*)d_in[11];
    const float* br    = (const float*)d_in[12];
    const float* wgt   = (const float*)d_in[13];
    float* out = (float*)d_out;

    const int N = in_sizes[0] / FIN;
    const int E = in_sizes[1] / 2;
    const int* erow = ei;
    const int* ecol = ei + E;

    static float *pR = 0, *pQK = 0, *pRn = 0, *pDeg = 0, *pDinv = 0,
                 *pInvden = 0, *pKv = 0, *pStats = 0, *pWqk = 0, *pBqk = 0;
    if (!pR) {
        cudaGetSymbolAddress((void**)&pR,     g_R);
        cudaGetSymbolAddress((void**)&pQK,    g_QK);
        cudaGetSymbolAddress((void**)&pRn,    g_Rn);
        cudaGetSymbolAddress((void**)&pDeg,   g_deg);
        cudaGetSymbolAddress((void**)&pDinv,  g_dinv);
        cudaGetSymbolAddress((void**)&pInvden,g_invden);
        cudaGetSymbolAddress((void**)&pKv,    g_kv);
        cudaGetSymbolAddress((void**)&pStats, g_stats);
        cudaGetSymbolAddress((void**)&pWqk,   g_Wqk);
        cudaGetSymbolAddress((void**)&pBqk,   g_bqk);
    }

    // degrees + symmetric norm weights
    zero_k  <<<(N + 255) / 256, 256>>>(pDeg, N);
    deg_acc <<<(E + 255) / 256, 256>>>(ecol, E);
    invsqrt_k<<<(N + 255) / 256, 256>>>(N);

    // fused [Wq|Wk] weight/bias buffer
    build_wqk<<<(H * 2 * H + 255) / 256, 256>>>(Wq, bq, Wk, bk);

    // R = relu(x @ W1 + b1)
    {
        dim3 g((H + 127) / 128, (N + 127) / 128);
        sgemm<1><<<g, 256>>>(x, FIN, W1, H, b1, pR, H, N, FIN, nullptr, nullptr);
    }

    // out = wgt[0] * (T0 @ Wr[0] + br[0])
    readout0<<<(N * 32 + 255) / 256, 256>>>(Wr, br, wgt, out, N);

    for (int it = 0; it < 3; it++) {
        // [q|k] = R @ [Wq|Wk] + [bq|bk]
        dim3 gqk((2 * H + 127) / 128, (N + 127) / 128);
        sgemm<0><<<gqk, 256>>>(pR, H, pWqk, 2 * H, pBqk, pQK, 2 * H, N, H, nullptr, nullptr);

        zero_k<<<(H * H + 255) / 256, 256>>>(pKv, H * H);
        zero_k<<<3, 256>>>(pStats, 2 + 2 * H);

        reduce_stats<<<(N + 127) / 128, 256>>>(N);
        kv_gemm<<<dim3(4, 4, (N + 1023) / 1024), 256>>>(N);
        finalize_s<<<1, 1>>>();
        den_kernel<<<(N * 32 + 255) / 256, 256>>>(N, (float)N);

        // Rn = attention output
        dim3 gqkv((H + 127) / 128, (N + 127) / 128);
        sgemm<2><<<gqkv, 256>>>(pQK, 2 * H, pKv, H, nullptr, pRn, H, N, H,
                                pStats + 2 + H, pInvden);

        // Rn += GCN(R)  (two 128-dim passes for L2 residency)
        long long nthr = (long long)E * 32;
        int nb = (int)((nthr + 255) / 256);
        gcn_edges<<<nb, 256>>>(erow, ecol, E, 0);
        gcn_edges<<<nb, 256>>>(erow, ecol, E, 128);

        // R = LN(alpha*Rn + (1-alpha)*R); out += wgt[it+1]*(R @ Wr[it+1] + br[it+1])
        blend_ln<<<(N * 32 + 255) / 256, 256>>>(alpha, gamma, beta, Wr, br, wgt,
                                                it + 1, out, N);
    }
}

// round 3
// speedup vs baseline: 1.2694x; 1.2694x over previous
#include <cuda_runtime.h>
#include <cuda_bf16.h>
#include <math.h>
#include <stdint.h>

#define H 256
#define FIN 58
#define N_MAX 100000

typedef __nv_bfloat16 bf16;

// ---------------- scratch (device globals; no allocation allowed) ------------
__device__ float g_R  [(size_t)N_MAX * H];        // current features fp32 (edges/LN)
__device__ float g_Rn [(size_t)N_MAX * H];        // conv output
__device__ bf16  g_Rh [(size_t)N_MAX * H];        // split-bf16 of R (hi)
__device__ bf16  g_Rl [(size_t)N_MAX * H];        // (lo)
__device__ bf16  g_RTh[(size_t)H * N_MAX];        // R^T (v^T) split planes
__device__ bf16  g_RTl[(size_t)H * N_MAX];
__device__ bf16  g_kTh[(size_t)H * N_MAX];        // k^T split planes
__device__ bf16  g_kTl[(size_t)H * N_MAX];
__device__ bf16  g_qkh[(size_t)N_MAX * 2 * H];    // [q|k] split planes
__device__ bf16  g_qkl[(size_t)N_MAX * 2 * H];
__device__ bf16  g_WqkTh[2 * H * H];              // [Wq|Wk]^T split (512 x 256)
__device__ bf16  g_WqkTl[2 * H * H];
__device__ bf16  g_kvTh[H * H];                   // kv^T split (256 x 256)
__device__ bf16  g_kvTl[H * H];
__device__ float g_kv [H * H];                    // k^T v fp32
__device__ float g_deg [N_MAX];
__device__ float g_dinv[N_MAX];
__device__ float g_invden[N_MAX];
__device__ float g_stats[2 + 2 * H];              // [q2, k2, ksum, vsum]
__device__ float g_s[1];

// ---------------- PTX helpers --------------------------------------------------
__device__ __forceinline__ uint32_t smem_u32(const void* p) {
    uint32_t a;
    asm("{ .reg .u64 t; cvta.to.shared.u64 t, %1; cvt.u32.u64 %0, t; }" : "=r"(a) : "l"(p));
    return a;
}
__device__ __forceinline__ void ldsm4(uint32_t* r, uint32_t addr) {
    asm volatile("ldmatrix.sync.aligned.m8n8.x4.shared.b16 {%0,%1,%2,%3}, [%4];"
                 : "=r"(r[0]), "=r"(r[1]), "=r"(r[2]), "=r"(r[3]) : "r"(addr));
}
__device__ __forceinline__ void mma16816(float* c, const uint32_t* a, uint32_t b0, uint32_t b1) {
    asm volatile("mma.sync.aligned.m16n8k16.row.col.f32.bf16.bf16.f32 "
                 "{%0,%1,%2,%3}, {%4,%5,%6,%7}, {%8,%9}, {%0,%1,%2,%3};"
                 : "+f"(c[0]), "+f"(c[1]), "+f"(c[2]), "+f"(c[3])
                 : "r"(a[0]), "r"(a[1]), "r"(a[2]), "r"(a[3]), "r"(b0), "r"(b1));
}
#define SW128(o) ((o) ^ (((o) >> 3) & 0x70))

// ---------------- tiny utility kernels ---------------------------------------
__global__ void zero_k(float* p, int n) {
    int i = blockIdx.x * blockDim.x + threadIdx.x;
    if (i < n) p[i] = 0.f;
}
__global__ void deg_acc(const int* __restrict__ col, int E) {
    int i = blockIdx.x * blockDim.x + threadIdx.x;
    if (i < E) atomicAdd(&g_deg[col[i]], 1.0f);
}
__global__ void invsqrt_k(int n) {
    int i = blockIdx.x * blockDim.x + threadIdx.x;
    if (i < n) {
        float d = g_deg[i];
        g_dinv[i] = (d > 0.f) ? 1.0f / sqrtf(d) : 0.f;
    }
}
__device__ __forceinline__ void split_store(float v, bf16* ph, bf16* pl, size_t idx) {
    bf16 h = __float2bfloat16(v);
    ph[idx] = h;
    pl[idx] = __float2bfloat16(v - __bfloat162float(h));
}
// [Wq|Wk]^T split planes: WqkT[n][k] = (n<256 ? Wq[k][n] : Wk[k][n-256])
__global__ void build_wqkT(const float* __restrict__ Wq, const float* __restrict__ Wk) {
    int idx = blockIdx.x * blockDim.x + threadIdx.x;
    if (idx >= 2 * H * H) return;
    int n = idx >> 8, k = idx & 255;
    float w = (n < H) ? Wq[k * H + n] : Wk[k * H + (n - H)];
    split_store(w, g_WqkTh, g_WqkTl, idx);
}
// kv^T split planes: kvT[d][m] = kv[m][d]
__global__ void build_kvT() {
    int idx = blockIdx.x * blockDim.x + threadIdx.x;
    if (idx >= H * H) return;
    int d = idx >> 8, m = idx & 255;
    split_store(g_kv[m * H + d], g_kvTh, g_kvTl, idx);
}
// tiled bf16 transpose: out[c][r] = in[r][c]; in rows x 256 cols
__global__ void transpose_bf16(const bf16* __restrict__ in, bf16* __restrict__ out,
                               int rows, int istride, int ostride) {
    __shared__ bf16 t[32][33];
    int r0 = blockIdx.x * 32, c0 = blockIdx.y * 32;
    for (int i = threadIdx.y; i < 32; i += 8) {
        int r = r0 + i, c = c0 + threadIdx.x;
        t[i][threadIdx.x] = (r < rows) ? in[(size_t)r * istride + c] : __float2bfloat16(0.f);
    }
    __syncthreads();
    for (int i = threadIdx.y; i < 32; i += 8) {
        int oc = r0 + threadIdx.x, orow = c0 + i;
        if (oc < rows) out[(size_t)orow * ostride + oc] = t[threadIdx.x][i];
    }
}

// ---------------- fp32 SGEMM for x@W1 (K=58) with relu + split epilogue -------
__global__ __launch_bounds__(256) void sgemm_relu(
    const float* __restrict__ A, int lda,
    const float* __restrict__ B, int ldb,
    const float* __restrict__ bias,
    float* __restrict__ C, int ldc,
    int M, int K,
    bf16* __restrict__ Ch, bf16* __restrict__ Cl)
{
    __shared__ float As[8][128];
    __shared__ float Bs[8][128];
    const int tid = threadIdx.x;
    const int row0 = blockIdx.y * 128, col0 = blockIdx.x * 128;
    const int tr = tid >> 4, tc = tid & 15;
    const int ar = tid >> 1, as_ = (tid & 1) * 4;
    const int bkr = tid >> 5, bc = (tid & 31) * 4;

    float acc[8][8] = {};
    const int ksteps = (K + 7) / 8;
    for (int kt = 0; kt < ksteps; kt++) {
        int k0 = kt * 8;
        {
            int r = row0 + ar;
            #pragma unroll
            for (int j = 0; j < 4; j++) {
                int k = k0 + as_ + j;
                As[as_ + j][ar] = (r < M && k < K) ? A[(size_t)r * lda + k] : 0.f;
            }
        }
        {
            int k = k0 + bkr;
            float4 v = make_float4(0.f, 0.f, 0.f, 0.f);
            if (k < K) v = *(const float4*)&B[(size_t)k * ldb + col0 + bc];
            *(float4*)&Bs[bkr][bc] = v;
        }
        __syncthreads();
        #pragma unroll
        for (int kk = 0; kk < 8; kk++) {
            float a[8], b[8];
            *(float4*)&a[0] = *(const float4*)&As[kk][tr * 8];
            *(float4*)&a[4] = *(const float4*)&As[kk][tr * 8 + 4];
            *(float4*)&b[0] = *(const float4*)&Bs[kk][tc * 8];
            *(float4*)&b[4] = *(const float4*)&Bs[kk][tc * 8 + 4];
            #pragma unroll
            for (int i = 0; i < 8; i++)
                #pragma unroll
                for (int j = 0; j < 8; j++)
                    acc[i][j] += a[i] * b[j];
        }
        __syncthreads();
    }

    float bb[8];
    #pragma unroll
    for (int j = 0; j < 8; j++) bb[j] = bias[col0 + tc * 8 + j];
    #pragma unroll
    for (int i = 0; i < 8; i++) {
        int r = row0 + tr * 8 + i;
        if (r >= M) continue;
        #pragma unroll
        for (int j = 0; j < 8; j++) {
            int c = col0 + tc * 8 + j;
            float val = fmaxf(acc[i][j] + bb[j], 0.f);
            size_t idx = (size_t)r * ldc + c;
            C[idx] = val;
            split_store(val, Ch, Cl, idx);
        }
    }
}

// ---------------- mma.sync split-bf16 GEMM ------------------------------------
// C[m,n] = sum_k A[m,k]*B[n,k], 3-term split (AhBh + AhBl + AlBh), fp32 acc.
// Tile: BM=128, BN=64, BK=64; 8 warps (4 M x 2 N), warp tile 32x32.
// EPI 0: qk (+bias, split-plane output)  EPI 1: attn  EPI 2: kv (atomic fp32)
template <int EPI>
__global__ __launch_bounds__(256, 2) void mma_gemm(
    const bf16* __restrict__ Ah, const bf16* __restrict__ Al, int lda,
    const bf16* __restrict__ Bh, const bf16* __restrict__ Bl, int ldb,
    int Mrows, int Ktot, int kchunk,
    const float* __restrict__ e0, const float* __restrict__ e1,
    float* __restrict__ outf, bf16* __restrict__ oh, bf16* __restrict__ ol)
{
    __shared__ alignas(1024) bf16 sAh[128 * 64];
    __shared__ alignas(1024) bf16 sAl[128 * 64];
    __shared__ alignas(1024) bf16 sBh[64 * 64];
    __shared__ alignas(1024) bf16 sBl[64 * 64];

    const int tid = threadIdx.x, wid = tid >> 5, lane = tid & 31;
    const int wm = (wid & 3) * 32;          // warp M offset in tile
    const int wn = (wid >> 2) * 32;         // warp N offset in tile
    const int row0 = blockIdx.x * 128;
    const int ncol0 = blockIdx.y * 64;
    const int k0 = blockIdx.z * kchunk;
    int kend = k0 + kchunk; if (kend > Ktot) kend = Ktot;

    const uint32_t aAh = smem_u32(sAh), aAl = smem_u32(sAl);
    const uint32_t aBh = smem_u32(sBh), aBl = smem_u32(sBl);
    char* cAh = (char*)sAh; char* cAl = (char*)sAl;
    char* cBh = (char*)sBh; char* cBl = (char*)sBl;

    float acc[2][4][4] = {};

    for (int ks = k0; ks < kend; ks += 64) {
        // ---- fill A tiles: 128 rows x 64 bf16 (hi+lo), SW128 swizzled -------
        #pragma unroll
        for (int it = 0; it < 4; it++) {
            int ch = tid + it * 256;
            int r = ch >> 3, c8 = ch & 7;
            int g = row0 + r;
            int kb = ks + c8 * 8;
            uint32_t off = SW128((uint32_t)(r * 128 + c8 * 16));
            int4 vh = make_int4(0, 0, 0, 0), vl = make_int4(0, 0, 0, 0);
            if (g < Mrows && kb + 8 <= kend) {
                vh = *(const int4*)&Ah[(size_t)g * lda + kb];
                vl = *(const int4*)&Al[(size_t)g * lda + kb];
            }
            *(int4*)(cAh + off) = vh;
            *(int4*)(cAl + off) = vl;
        }
        // ---- fill B tiles: 64 rows x 64 bf16 --------------------------------
        #pragma unroll
        for (int it = 0; it < 2; it++) {
            int ch = tid + it * 256;
            int r = ch >> 3, c8 = ch & 7;
            int gn = ncol0 + r;
            int kb = ks + c8 * 8;
            uint32_t off = SW128((uint32_t)(r * 128 + c8 * 16));
            int4 vh = make_int4(0, 0, 0, 0), vl = make_int4(0, 0, 0, 0);
            if (kb + 8 <= kend) {
                vh = *(const int4*)&Bh[(size_t)gn * ldb + kb];
                vl = *(const int4*)&Bl[(size_t)gn * ldb + kb];
            }
            *(int4*)(cBh + off) = vh;
            *(int4*)(cBl + off) = vl;
        }
        __syncthreads();

        #pragma unroll
        for (int kc = 0; kc < 4; kc++) {
            uint32_t ah[2][4], al[2][4], bh[2][4], bl[2][4];
            #pragma unroll
            for (int mt = 0; mt < 2; mt++) {
                uint32_t off = SW128((uint32_t)((wm + mt * 16 + (lane & 15)) * 128 +
                                                (kc * 16 + (lane >> 4) * 8) * 2));
                ldsm4(ah[mt], aAh + off);
                ldsm4(al[mt], aAl + off);
            }
            #pragma unroll
            for (int ntp = 0; ntp < 2; ntp++) {
                uint32_t off = SW128((uint32_t)((wn + ntp * 16 + ((lane >> 4) & 1) * 8 + (lane & 7)) * 128 +
                                                (kc * 16 + ((lane >> 3) & 1) * 8) * 2));
                ldsm4(bh[ntp], aBh + off);
                ldsm4(bl[ntp], aBl + off);
            }
            #pragma unroll
            for (int mt = 0; mt < 2; mt++)
                #pragma unroll
                for (int nt = 0; nt < 4; nt++) {
                    uint32_t b0h = bh[nt >> 1][(nt & 1) * 2], b1h = bh[nt >> 1][(nt & 1) * 2 + 1];
                    uint32_t b0l = bl[nt >> 1][(nt & 1) * 2], b1l = bl[nt >> 1][(nt & 1) * 2 + 1];
                    mma16816(acc[mt][nt], ah[mt], b0h, b1h);
                    mma16816(acc[mt][nt], ah[mt], b0l, b1l);
                    mma16816(acc[mt][nt], al[mt], b0h, b1h);
                }
        }
        __syncthreads();
    }

    // ---- epilogue ------------------------------------------------------------
    float s_val = 0.f;
    if (EPI == 1) s_val = g_s[0];
    #pragma unroll
    for (int mt = 0; mt < 2; mt++) {
        #pragma unroll
        for (int rg = 0; rg < 4; rg++) {
            int r = row0 + wm + mt * 16 + (lane >> 2) + ((rg >> 1) & 1) * 8;
            if (r >= Mrows) continue;
            #pragma unroll
            for (int nt = 0; nt < 4; nt++) {
                int c = ncol0 + wn + nt * 8 + (lane & 3) * 2 + (rg & 1);
                float d = acc[mt][nt][rg];
                if (EPI == 0) {
                    float bias = (c < H) ? e0[c] : e1[c - H];
                    split_store(d + bias, oh, ol, (size_t)r * 512 + c);
                } else if (EPI == 1) {
                    float v = (d * s_val + g_stats[2 + H + c]) * g_invden[r];
                    outf[(size_t)r * H + c] = v;
                } else {
                    atomicAdd(&g_kv[(size_t)r * H + c], d);
                }
            }
        }
    }
}

// ---------------- stats: ||q||^2, ||k||^2, colsum(k), colsum(v) ---------------
__global__ __launch_bounds__(256) void reduce_stats(int M) {
    int t = threadIdx.x;
    int r0 = blockIdx.x * 128;
    int rend = r0 + 128; if (rend > M) rend = M;
    float q2 = 0.f, k2 = 0.f, ks = 0.f, vs = 0.f;
    for (int r = r0; r < rend; r++) {
        size_t b = (size_t)r * 512;
        float qv  = __bfloat162float(g_qkh[b + t])       + __bfloat162float(g_qkl[b + t]);
        float kvv = __bfloat162float(g_qkh[b + 256 + t]) + __bfloat162float(g_qkl[b + 256 + t]);
        float vv  = g_R[(size_t)r * 256 + t];
        q2 += qv * qv; k2 += kvv * kvv; ks += kvv; vs += vv;
    }
    atomicAdd(&g_stats[2 + t], ks);
    atomicAdd(&g_stats[2 + 256 + t], vs);
    __shared__ float sq[256], sk[256];
    sq[t] = q2; sk[t] = k2; __syncthreads();
    for (int o = 128; o > 0; o >>= 1) {
        if (t < o) { sq[t] += sq[t + o]; sk[t] += sk[t + o]; }
        __syncthreads();
    }
    if (t == 0) { atomicAdd(&g_stats[0], sq[0]); atomicAdd(&g_stats[1], sk[0]); }
}

__global__ void finalize_s() {
    g_s[0] = rsqrtf(g_stats[0]) * rsqrtf(g_stats[1]);
}

// ---------------- per-row denominator: 1 / (s * (q . ksum) + N) ---------------
__global__ void den_kernel(int M, float fN) {
    int gw = (blockIdx.x * blockDim.x + threadIdx.x) >> 5;
    int l = threadIdx.x & 31;
    if (gw >= M) return;
    size_t base = (size_t)gw * 512;
    float sum = 0.f;
    #pragma unroll
    for (int j = 0; j < 8; j++) {
        int idx = j * 32 + l;
        float qv = __bfloat162float(g_qkh[base + idx]) + __bfloat162float(g_qkl[base + idx]);
        sum += qv * g_stats[2 + idx];
    }
    #pragma unroll
    for (int o = 16; o > 0; o >>= 1) sum += __shfl_xor_sync(0xffffffffu, sum, o);
    if (l == 0) g_invden[gw] = 1.0f / (g_s[0] * sum + fN);
}

// ---------------- GCN scatter: Rn[c] += dinv[r]*dinv[c] * R[r] ----------------
__global__ void gcn_edges(const int* __restrict__ erow, const int* __restrict__ ecol,
                          int E, int dimoff) {
    long long t = (long long)blockIdx.x * blockDim.x + threadIdx.x;
    long long gw = t >> 5;
    if (gw >= E) return;
    int l = threadIdx.x & 31;
    int r = erow[gw], c = ecol[gw];
    float wt = g_dinv[r] * g_dinv[c];
    float4 v = *(const float4*)&g_R[(size_t)r * 256 + dimoff + l * 4];
    float* dst = &g_Rn[(size_t)c * 256 + dimoff + l * 4];
    asm volatile("red.global.add.v4.f32 [%0], {%1,%2,%3,%4};"
                 :: "l"(dst), "f"(v.x * wt), "f"(v.y * wt), "f"(v.z * wt), "f"(v.w * wt)
                 : "memory");
}

// ---------------- blend + LayerNorm + split write + readout accumulate --------
__global__ void blend_ln(const float* __restrict__ alpha_p,
                         const float* __restrict__ gamma, const float* __restrict__ beta,
                         const float* __restrict__ Wr, const float* __restrict__ br,
                         const float* __restrict__ wgt, int sidx,
                         float* __restrict__ out, int M)
{
    int gw = (blockIdx.x * blockDim.x + threadIdx.x) >> 5;
    int l = threadIdx.x & 31;
    if (gw >= M) return;
    float al = alpha_p[0];
    size_t base = (size_t)gw * 256;
    float h[8]; float sum = 0.f, sq = 0.f;
    #pragma unroll
    for (int j = 0; j < 8; j++) {
        int idx = j * 32 + l;
        float v = al * g_Rn[base + idx] + (1.f - al) * g_R[base + idx];
        h[j] = v; sum += v; sq += v * v;
    }
    #pragma unroll
    for (int o = 16; o > 0; o >>= 1) {
        sum += __shfl_xor_sync(0xffffffffu, sum, o);
        sq  += __shfl_xor_sync(0xffffffffu, sq, o);
    }
    float mu  = sum * (1.f / 256.f);
    float var = sq * (1.f / 256.f) - mu * mu;
    float rstd = rsqrtf(var + 1e-5f);
    const float* wr = Wr + sidx * 256;
    float dot = 0.f;
    #pragma unroll
    for (int j = 0; j < 8; j++) {
        int idx = j * 32 + l;
        float y = (h[j] - mu) * rstd * gamma[idx] + beta[idx];
        g_R[base + idx] = y;
        split_store(y, g_Rh, g_Rl, base + idx);
        dot += y * wr[idx];
    }
    #pragma unroll
    for (int o = 16; o > 0; o >>= 1) dot += __shfl_xor_sync(0xffffffffu, dot, o);
    if (l == 0) out[gw] += wgt[sidx] * (dot + br[sidx]);
}

// ---------------- stage-0 readout (overwrites poisoned d_out) -----------------
__global__ void readout0(const float* __restrict__ Wr, const float* __restrict__ br,
                         const float* __restrict__ wgt, float* __restrict__ out, int M)
{
    int gw = (blockIdx.x * blockDim.x + threadIdx.x) >> 5;
    int l = threadIdx.x & 31;
    if (gw >= M) return;
    float dot = 0.f;
    #pragma unroll
    for (int j = 0; j < 8; j++) {
        int idx = j * 32 + l;
        dot += g_R[(size_t)gw * 256 + idx] * Wr[idx];
    }
    #pragma unroll
    for (int o = 16; o > 0; o >>= 1) dot += __shfl_xor_sync(0xffffffffu, dot, o);
    if (l == 0) out[gw] = wgt[0] * (dot + br[0]);
}

// ---------------- host orchestration ------------------------------------------
extern "C" void kernel_launch(void* const* d_in, const int* in_sizes, int n_in,
                              void* d_out, int out_size)
{
    const float* x     = (const float*)d_in[0];
    const int*   ei    = (const int*)  d_in[1];
    const float* W1    = (const float*)d_in[2];
    const float* b1    = (const float*)d_in[3];
    const float* Wq    = (const float*)d_in[4];
    const float* bq    = (const float*)d_in[5];
    const float* Wk    = (const float*)d_in[6];
    const float* bk    = (const float*)d_in[7];
    const float* gamma = (const float*)d_in[8];
    const float* beta  = (const float*)d_in[9];
    const float* alpha = (const float*)d_in[10];
    const float* Wr    = (const float*)d_in[11];
    const float* br    = (const float*)d_in[12];
    const float* wgt   = (const float*)d_in[13];
    float* out = (float*)d_out;

    const int N = in_sizes[0] / FIN;
    const int E = in_sizes[1] / 2;
    const int* erow = ei;
    const int* ecol = ei + E;

    static float *pR = 0, *pRn = 0, *pDeg = 0, *pKv = 0, *pStats = 0;
    static bf16 *pRh = 0, *pRl = 0, *pRTh = 0, *pRTl = 0, *pkTh = 0, *pkTl = 0,
                *pqkh = 0, *pqkl = 0, *pWTh = 0, *pWTl = 0, *pkvTh = 0, *pkvTl = 0;
    if (!pR) {
        cudaGetSymbolAddress((void**)&pR,    g_R);
        cudaGetSymbolAddress((void**)&pRn,   g_Rn);
        cudaGetSymbolAddress((void**)&pDeg,  g_deg);
        cudaGetSymbolAddress((void**)&pKv,   g_kv);
        cudaGetSymbolAddress((void**)&pStats,g_stats);
        cudaGetSymbolAddress((void**)&pRh,   g_Rh);
        cudaGetSymbolAddress((void**)&pRl,   g_Rl);
        cudaGetSymbolAddress((void**)&pRTh,  g_RTh);
        cudaGetSymbolAddress((void**)&pRTl,  g_RTl);
        cudaGetSymbolAddress((void**)&pkTh,  g_kTh);
        cudaGetSymbolAddress((void**)&pkTl,  g_kTl);
        cudaGetSymbolAddress((void**)&pqkh,  g_qkh);
        cudaGetSymbolAddress((void**)&pqkl,  g_qkl);
        cudaGetSymbolAddress((void**)&pWTh,  g_WqkTh);
        cudaGetSymbolAddress((void**)&pWTl,  g_WqkTl);
        cudaGetSymbolAddress((void**)&pkvTh, g_kvTh);
        cudaGetSymbolAddress((void**)&pkvTl, g_kvTl);
    }

    const int mtiles = (N + 127) / 128;
    const int tgrid = (N * 32 + 255) / 256;

    // degrees + symmetric norm weights
    zero_k   <<<(N + 255) / 256, 256>>>(pDeg, N);
    deg_acc  <<<(E + 255) / 256, 256>>>(ecol, E);
    invsqrt_k<<<(N + 255) / 256, 256>>>(N);

    // [Wq|Wk]^T split planes
    build_wqkT<<<(2 * H * H + 255) / 256, 256>>>(Wq, Wk);

    // R = relu(x @ W1 + b1), with split-bf16 side output
    {
        dim3 g((H + 127) / 128, (N + 127) / 128);
        sgemm_relu<<<g, 256>>>(x, FIN, W1, H, b1, pR, H, N, FIN, pRh, pRl);
    }

    // out = wgt[0] * (T0 @ Wr[0] + br[0])
    readout0<<<tgrid, 256>>>(Wr, br, wgt, out, N);

    for (int it = 0; it < 3; it++) {
        // [q|k] = R @ [Wq|Wk] + bias, split-bf16 output planes
        mma_gemm<0><<<dim3(mtiles, 8, 1), 256>>>(
            pRh, pRl, 256, pWTh, pWTl, 256, N, 256, 256,
            bq, bk, nullptr, pqkh, pqkl);

        zero_k<<<(H * H + 255) / 256, 256>>>(pKv, H * H);
        zero_k<<<3, 256>>>(pStats, 2 + 2 * H);

        reduce_stats<<<(N + 127) / 128, 256>>>(N);

        // transposed split planes: k^T and v^T(=R^T)
        {
            dim3 g((N + 31) / 32, 8), b(32, 8);
            transpose_bf16<<<g, b>>>(pqkh + 256, pkTh, N, 512, N);
            transpose_bf16<<<g, b>>>(pqkl + 256, pkTl, N, 512, N);
            transpose_bf16<<<g, b>>>(pRh, pRTh, N, 256, N);
            transpose_bf16<<<g, b>>>(pRl, pRTl, N, 256, N);
        }

        // kv = k^T @ v  (split-K over N, atomic fp32 merge)
        {
            int zchunks = (N + 511) / 512;
            mma_gemm<2><<<dim3(2, 4, zchunks), 256>>>(
                pkTh, pkTl, N, pRTh, pRTl, N, 256, N, 512,
                nullptr, nullptr, nullptr, nullptr, nullptr);
        }

        finalize_s<<<1, 1>>>();
        den_kernel<<<tgrid, 256>>>(N, (float)N);
        build_kvT<<<(H * H + 255) / 256, 256>>>();

        // Rn = (q @ kv * s + vsum) * invden
        mma_gemm<1><<<dim3(mtiles, 4, 1), 256>>>(
            pqkh, pqkl, 512, pkvTh, pkvTl, 256, N, 256, 256,
            nullptr, nullptr, pRn, nullptr, nullptr);

        // Rn += GCN(R)  (two 128-dim passes for L2 residency)
        long long nthr = (long long)E * 32;
        int nb = (int)((nthr + 255) / 256);
        gcn_edges<<<nb, 256>>>(erow, ecol, E, 0);
        gcn_edges<<<nb, 256>>>(erow, ecol, E, 128);

        // R = LN(alpha*Rn + (1-alpha)*R) (+ split planes); readout accumulate
        blend_ln<<<tgrid, 256>>>(alpha, gamma, beta, Wr, br, wgt, it + 1, out, N);
    }
}

// round 4
// speedup vs baseline: 1.9156x; 1.5091x over previous
#include <cuda_runtime.h>
#include <cuda_bf16.h>
#include <math.h>
#include <stdint.h>

#define H 256
#define FIN 58
#define N_MAX 100000
#define E_MAX 3200000

typedef __nv_bfloat16 bf16;

// ---------------- scratch (device globals; no allocation allowed) ------------
__device__ float g_R  [(size_t)N_MAX * H];
__device__ float g_Rn [(size_t)N_MAX * H];
__device__ bf16  g_Rh [(size_t)N_MAX * H];
__device__ bf16  g_Rl [(size_t)N_MAX * H];
__device__ bf16  g_RTh[(size_t)H * N_MAX];
__device__ bf16  g_RTl[(size_t)H * N_MAX];
__device__ bf16  g_kTh[(size_t)H * N_MAX];
__device__ bf16  g_kTl[(size_t)H * N_MAX];
__device__ bf16  g_qkh[(size_t)N_MAX * 2 * H];
__device__ bf16  g_qkl[(size_t)N_MAX * 2 * H];
__device__ bf16  g_WqkTh[2 * H * H];
__device__ bf16  g_WqkTl[2 * H * H];
__device__ bf16  g_kvTh[H * H];
__device__ bf16  g_kvTl[H * H];
__device__ float g_kv [H * H];
__device__ float g_dinv[N_MAX];
__device__ float g_invden[N_MAX];
__device__ float g_stats[2 + 2 * H];
__device__ float g_s[1];
// CSR structures
__device__ int   g_degi[N_MAX];
__device__ int   g_cur [N_MAX];
__device__ int   g_off [N_MAX + 1];
__device__ int   g_bsum[128];
__device__ int   g_esrc[E_MAX];
__device__ float g_ew  [E_MAX];

// ---------------- PTX helpers --------------------------------------------------
__device__ __forceinline__ uint32_t smem_u32(const void* p) {
    uint32_t a;
    asm("{ .reg .u64 t; cvta.to.shared.u64 t, %1; cvt.u32.u64 %0, t; }" : "=r"(a) : "l"(p));
    return a;
}
__device__ __forceinline__ void ldsm4(uint32_t* r, uint32_t addr) {
    asm volatile("ldmatrix.sync.aligned.m8n8.x4.shared.b16 {%0,%1,%2,%3}, [%4];"
                 : "=r"(r[0]), "=r"(r[1]), "=r"(r[2]), "=r"(r[3]) : "r"(addr));
}
__device__ __forceinline__ void mma16816(float* c, const uint32_t* a, uint32_t b0, uint32_t b1) {
    asm volatile("mma.sync.aligned.m16n8k16.row.col.f32.bf16.bf16.f32 "
                 "{%0,%1,%2,%3}, {%4,%5,%6,%7}, {%8,%9}, {%0,%1,%2,%3};"
                 : "+f"(c[0]), "+f"(c[1]), "+f"(c[2]), "+f"(c[3])
                 : "r"(a[0]), "r"(a[1]), "r"(a[2]), "r"(a[3]), "r"(b0), "r"(b1));
}
__device__ __forceinline__ void cpa16(uint32_t dst, const void* src, bool pred) {
    int sz = pred ? 16 : 0;
    asm volatile("cp.async.cg.shared.global [%0], [%1], 16, %2;"
                 :: "r"(dst), "l"(src), "r"(sz));
}
#define CP_COMMIT() asm volatile("cp.async.commit_group;" ::: "memory")
#define SW128(o) ((o) ^ (((o) >> 3) & 0x70))

// ---------------- tiny utility kernels ---------------------------------------
__global__ void zero_k(float* p, int n) {
    int i = blockIdx.x * blockDim.x + threadIdx.x;
    if (i < n) p[i] = 0.f;
}
__global__ void zero_i2(int n) {
    int i = blockIdx.x * blockDim.x + threadIdx.x;
    if (i < n) { g_degi[i] = 0; g_cur[i] = 0; }
}
__global__ void cnt_deg(const int* __restrict__ col, int E) {
    int i = blockIdx.x * blockDim.x + threadIdx.x;
    if (i < E) atomicAdd(&g_degi[col[i]], 1);
}
__global__ void invsqrt_k(int n) {
    int i = blockIdx.x * blockDim.x + threadIdx.x;
    if (i < n) {
        int d = g_degi[i];
        g_dinv[i] = (d > 0) ? rsqrtf((float)d) : 0.f;
    }
}
// ---- 2-level exclusive scan of g_degi -> g_off -------------------------------
__global__ __launch_bounds__(256) void scan1(int n) {
    __shared__ int s[256];
    int b = blockIdx.x, t = threadIdx.x;
    int base = b * 1024 + t * 4;
    int v0 = 0, v1 = 0, v2 = 0, v3 = 0;
    if (base + 0 < n) v0 = g_degi[base + 0];
    if (base + 1 < n) v1 = g_degi[base + 1];
    if (base + 2 < n) v2 = g_degi[base + 2];
    if (base + 3 < n) v3 = g_degi[base + 3];
    int tsum = v0 + v1 + v2 + v3;
    s[t] = tsum;
    __syncthreads();
    for (int o = 1; o < 256; o <<= 1) {
        int x = 0;
        if (t >= o) x = s[t - o];
        __syncthreads();
        s[t] += x;
        __syncthreads();
    }
    int ex = s[t] - tsum;
    if (base + 0 < n) g_off[base + 0] = ex;
    if (base + 1 < n) g_off[base + 1] = ex + v0;
    if (base + 2 < n) g_off[base + 2] = ex + v0 + v1;
    if (base + 3 < n) g_off[base + 3] = ex + v0 + v1 + v2;
    if (t == 255) g_bsum[b] = s[255];
}
__global__ void scan2(int nb) {
    __shared__ int s[128];
    int t = threadIdx.x;
    int v = (t < nb) ? g_bsum[t] : 0;
    s[t] = v;
    __syncthreads();
    for (int o = 1; o < 128; o <<= 1) {
        int x = 0;
        if (t >= o) x = s[t - o];
        __syncthreads();
        s[t] += x;
        __syncthreads();
    }
    g_bsum[t] = s[t] - v;
}
__global__ void scan3(int n, int E) {
    int i = blockIdx.x * blockDim.x + threadIdx.x;
    if (i < n) g_off[i] += g_bsum[i >> 10];
    if (i == 0) g_off[n] = E;
}
__global__ void edge_scatter(const int* __restrict__ erow, const int* __restrict__ ecol, int E) {
    int e = blockIdx.x * blockDim.x + threadIdx.x;
    if (e >= E) return;
    int c = ecol[e], r = erow[e];
    int pos = g_off[c] + atomicAdd(&g_cur[c], 1);
    g_esrc[pos] = r;
    g_ew[pos] = g_dinv[r] * g_dinv[c];
}

__device__ __forceinline__ void split_store(float v, bf16* ph, bf16* pl, size_t idx) {
    bf16 h = __float2bfloat16(v);
    ph[idx] = h;
    pl[idx] = __float2bfloat16(v - __bfloat162float(h));
}
__global__ void build_wqkT(const float* __restrict__ Wq, const float* __restrict__ Wk) {
    int idx = blockIdx.x * blockDim.x + threadIdx.x;
    if (idx >= 2 * H * H) return;
    int n = idx >> 8, k = idx & 255;
    float w = (n < H) ? Wq[k * H + n] : Wk[k * H + (n - H)];
    split_store(w, g_WqkTh, g_WqkTl, idx);
}
__global__ void build_kvT() {
    int idx = blockIdx.x * blockDim.x + threadIdx.x;
    if (idx >= H * H) return;
    int d = idx >> 8, m = idx & 255;
    split_store(g_kv[m * H + d], g_kvTh, g_kvTl, idx);
}
__global__ void transpose_bf16(const bf16* __restrict__ in, bf16* __restrict__ out,
                               int rows, int istride, int ostride) {
    __shared__ bf16 t[32][33];
    int r0 = blockIdx.x * 32, c0 = blockIdx.y * 32;
    for (int i = threadIdx.y; i < 32; i += 8) {
        int r = r0 + i, c = c0 + threadIdx.x;
        t[i][threadIdx.x] = (r < rows) ? in[(size_t)r * istride + c] : __float2bfloat16(0.f);
    }
    __syncthreads();
    for (int i = threadIdx.y; i < 32; i += 8) {
        int oc = r0 + threadIdx.x, orow = c0 + i;
        if (oc < rows) out[(size_t)orow * ostride + oc] = t[threadIdx.x][i];
    }
}

// ---------------- fp32 SGEMM for x@W1 (K=58) with relu + split epilogue -------
__global__ __launch_bounds__(256) void sgemm_relu(
    const float* __restrict__ A, int lda,
    const float* __restrict__ B, int ldb,
    const float* __restrict__ bias,
    float* __restrict__ C, int ldc,
    int M, int K,
    bf16* __restrict__ Ch, bf16* __restrict__ Cl)
{
    __shared__ float As[8][128];
    __shared__ float Bs[8][128];
    const int tid = threadIdx.x;
    const int row0 = blockIdx.y * 128, col0 = blockIdx.x * 128;
    const int tr = tid >> 4, tc = tid & 15;
    const int ar = tid >> 1, as_ = (tid & 1) * 4;
    const int bkr = tid >> 5, bc = (tid & 31) * 4;

    float acc[8][8] = {};
    const int ksteps = (K + 7) / 8;
    for (int kt = 0; kt < ksteps; kt++) {
        int k0 = kt * 8;
        {
            int r = row0 + ar;
            #pragma unroll
            for (int j = 0; j < 4; j++) {
                int k = k0 + as_ + j;
                As[as_ + j][ar] = (r < M && k < K) ? A[(size_t)r * lda + k] : 0.f;
            }
        }
        {
            int k = k0 + bkr;
            float4 v = make_float4(0.f, 0.f, 0.f, 0.f);
            if (k < K) v = *(const float4*)&B[(size_t)k * ldb + col0 + bc];
            *(float4*)&Bs[bkr][bc] = v;
        }
        __syncthreads();
        #pragma unroll
        for (int kk = 0; kk < 8; kk++) {
            float a[8], b[8];
            *(float4*)&a[0] = *(const float4*)&As[kk][tr * 8];
            *(float4*)&a[4] = *(const float4*)&As[kk][tr * 8 + 4];
            *(float4*)&b[0] = *(const float4*)&Bs[kk][tc * 8];
            *(float4*)&b[4] = *(const float4*)&Bs[kk][tc * 8 + 4];
            #pragma unroll
            for (int i = 0; i < 8; i++)
                #pragma unroll
                for (int j = 0; j < 8; j++)
                    acc[i][j] += a[i] * b[j];
        }
        __syncthreads();
    }

    float bb[8];
    #pragma unroll
    for (int j = 0; j < 8; j++) bb[j] = bias[col0 + tc * 8 + j];
    #pragma unroll
    for (int i = 0; i < 8; i++) {
        int r = row0 + tr * 8 + i;
        if (r >= M) continue;
        #pragma unroll
        for (int j = 0; j < 8; j++) {
            int c = col0 + tc * 8 + j;
            float val = fmaxf(acc[i][j] + bb[j], 0.f);
            size_t idx = (size_t)r * ldc + c;
            C[idx] = val;
            split_store(val, Ch, Cl, idx);
        }
    }
}

// ---------------- mma.sync split-bf16 GEMM, 2-stage cp.async pipeline ---------
// C[m,n] = sum_k A[m,k]*B[n,k]; BM=128 BN=64 BK=64; 8 warps 4x2; warp 32x32.
// Stage layout: [Ah 16K | Al 16K | Bh 8K | Bl 8K] = 48K; 2 stages = 96K dynamic.
#define STAGE_BYTES 49152
template <int EPI>
__global__ __launch_bounds__(256, 2) void mma_gemm(
    const bf16* __restrict__ Ah_, const bf16* __restrict__ Al_, int lda,
    const bf16* __restrict__ Bh_, const bf16* __restrict__ Bl_, int ldb,
    int Mrows, int Ktot, int kchunk,
    const float* __restrict__ e0, const float* __restrict__ e1,
    float* __restrict__ outf, bf16* __restrict__ oh, bf16* __restrict__ ol)
{
    extern __shared__ char smem[];
    const int tid = threadIdx.x, wid = tid >> 5, lane = tid & 31;
    const int wm = (wid & 3) * 32;
    const int wn = (wid >> 2) * 32;
    const int row0 = blockIdx.x * 128;
    const int ncol0 = blockIdx.y * 64;
    const int k0 = blockIdx.z * kchunk;
    int kend = k0 + kchunk; if (kend > Ktot) kend = Ktot;
    const uint32_t sbase = smem_u32(smem);

    auto fill = [&](int stage, int ks) {
        uint32_t sa = sbase + stage * STAGE_BYTES;
        #pragma unroll
        for (int it = 0; it < 4; it++) {
            int ch = tid + it * 256;
            int r = ch >> 3, c8 = ch & 7;
            int g = row0 + r;
            int kb = ks + c8 * 8;
            uint32_t off = SW128((uint32_t)(r * 128 + c8 * 16));
            bool p = (g < Mrows) && (kb + 8 <= kend);
            const bf16* ph = p ? &Ah_[(size_t)g * lda + kb] : Ah_;
            const bf16* pl = p ? &Al_[(size_t)g * lda + kb] : Al_;
            cpa16(sa + off, ph, p);
            cpa16(sa + 16384 + off, pl, p);
        }
        #pragma unroll
        for (int it = 0; it < 2; it++) {
            int ch = tid + it * 256;
            int r = ch >> 3, c8 = ch & 7;
            int gn = ncol0 + r;
            int kb = ks + c8 * 8;
            uint32_t off = SW128((uint32_t)(r * 128 + c8 * 16));
            bool p = (kb + 8 <= kend);
            const bf16* ph = p ? &Bh_[(size_t)gn * ldb + kb] : Bh_;
            const bf16* pl = p ? &Bl_[(size_t)gn * ldb + kb] : Bl_;
            cpa16(sa + 32768 + off, ph, p);
            cpa16(sa + 40960 + off, pl, p);
        }
    };

    float acc[2][4][4] = {};
    int stage = 0;
    fill(0, k0);
    CP_COMMIT();

    for (int ks = k0; ks < kend; ks += 64) {
        int nxt = ks + 64;
        if (nxt < kend) {
            fill(stage ^ 1, nxt);
            CP_COMMIT();
            asm volatile("cp.async.wait_group 1;" ::: "memory");
        } else {
            asm volatile("cp.async.wait_group 0;" ::: "memory");
        }
        __syncthreads();

        uint32_t base = sbase + stage * STAGE_BYTES;
        #pragma unroll
        for (int kc = 0; kc < 4; kc++) {
            uint32_t ah[2][4], al[2][4], bh[2][4], bl[2][4];
            #pragma unroll
            for (int mt = 0; mt < 2; mt++) {
                uint32_t off = SW128((uint32_t)((wm + mt * 16 + (lane & 15)) * 128 +
                                                (kc * 16 + (lane >> 4) * 8) * 2));
                ldsm4(ah[mt], base + off);
                ldsm4(al[mt], base + 16384 + off);
            }
            #pragma unroll
            for (int ntp = 0; ntp < 2; ntp++) {
                uint32_t off = SW128((uint32_t)((wn + ntp * 16 + ((lane >> 4) & 1) * 8 + (lane & 7)) * 128 +
                                                (kc * 16 + ((lane >> 3) & 1) * 8) * 2));
                ldsm4(bh[ntp], base + 32768 + off);
                ldsm4(bl[ntp], base + 40960 + off);
            }
            #pragma unroll
            for (int mt = 0; mt < 2; mt++)
                #pragma unroll
                for (int nt = 0; nt < 4; nt++) {
                    uint32_t b0h = bh[nt >> 1][(nt & 1) * 2], b1h = bh[nt >> 1][(nt & 1) * 2 + 1];
                    uint32_t b0l = bl[nt >> 1][(nt & 1) * 2], b1l = bl[nt >> 1][(nt & 1) * 2 + 1];
                    mma16816(acc[mt][nt], ah[mt], b0h, b1h);
                    mma16816(acc[mt][nt], ah[mt], b0l, b1l);
                    mma16816(acc[mt][nt], al[mt], b0h, b1h);
                }
        }
        __syncthreads();
        stage ^= 1;
    }

    // ---- epilogue ------------------------------------------------------------
    float s_val = 0.f;
    if (EPI == 1) s_val = g_s[0];
    #pragma unroll
    for (int mt = 0; mt < 2; mt++) {
        #pragma unroll
        for (int rg = 0; rg < 4; rg++) {
            int r = row0 + wm + mt * 16 + (lane >> 2) + ((rg >> 1) & 1) * 8;
            if (r >= Mrows) continue;
            #pragma unroll
            for (int nt = 0; nt < 4; nt++) {
                int c = ncol0 + wn + nt * 8 + (lane & 3) * 2 + (rg & 1);
                float d = acc[mt][nt][rg];
                if (EPI == 0) {
                    float bias = (c < H) ? e0[c] : e1[c - H];
                    split_store(d + bias, oh, ol, (size_t)r * 512 + c);
                } else if (EPI == 1) {
                    float v = (d * s_val + g_stats[2 + H + c]) * g_invden[r];
                    outf[(size_t)r * H + c] = v;
                } else {
                    atomicAdd(&g_kv[(size_t)r * H + c], d);
                }
            }
        }
    }
}

// ---------------- stats: ||q||^2, ||k||^2, colsum(k), colsum(v) ---------------
__global__ __launch_bounds__(256) void reduce_stats(int M) {
    int t = threadIdx.x;
    int r0 = blockIdx.x * 128;
    int rend = r0 + 128; if (rend > M) rend = M;
    float q2 = 0.f, k2 = 0.f, ks = 0.f, vs = 0.f;
    for (int r = r0; r < rend; r++) {
        size_t b = (size_t)r * 512;
        float qv  = __bfloat162float(g_qkh[b + t])       + __bfloat162float(g_qkl[b + t]);
        float kvv = __bfloat162float(g_qkh[b + 256 + t]) + __bfloat162float(g_qkl[b + 256 + t]);
        float vv  = g_R[(size_t)r * 256 + t];
        q2 += qv * qv; k2 += kvv * kvv; ks += kvv; vs += vv;
    }
    atomicAdd(&g_stats[2 + t], ks);
    atomicAdd(&g_stats[2 + 256 + t], vs);
    __shared__ float sq[256], sk[256];
    sq[t] = q2; sk[t] = k2; __syncthreads();
    for (int o = 128; o > 0; o >>= 1) {
        if (t < o) { sq[t] += sq[t + o]; sk[t] += sk[t + o]; }
        __syncthreads();
    }
    if (t == 0) { atomicAdd(&g_stats[0], sq[0]); atomicAdd(&g_stats[1], sk[0]); }
}

__global__ void finalize_s() {
    g_s[0] = rsqrtf(g_stats[0]) * rsqrtf(g_stats[1]);
}

__global__ void den_kernel(int M, float fN) {
    int gw = (blockIdx.x * blockDim.x + threadIdx.x) >> 5;
    int l = threadIdx.x & 31;
    if (gw >= M) return;
    size_t base = (size_t)gw * 512;
    float sum = 0.f;
    #pragma unroll
    for (int j = 0; j < 8; j++) {
        int idx = j * 32 + l;
        float qv = __bfloat162float(g_qkh[base + idx]) + __bfloat162float(g_qkl[base + idx]);
        sum += qv * g_stats[2 + idx];
    }
    #pragma unroll
    for (int o = 16; o > 0; o >>= 1) sum += __shfl_xor_sync(0xffffffffu, sum, o);
    if (l == 0) g_invden[gw] = 1.0f / (g_s[0] * sum + fN);
}

// ---------------- GCN gather: Rn[c] += sum_e w[e] * R[src[e]] ----------------
// One warp per destination node; CSR in-edges; no atomics.
__global__ __launch_bounds__(256) void gcn_gather(int Nn) {
    int warp = (blockIdx.x * blockDim.x + threadIdx.x) >> 5;
    if (warp >= Nn) return;
    int l = threadIdx.x & 31;
    int beg = g_off[warp], end = g_off[warp + 1];
    if (beg == end) return;
    float4 a0 = make_float4(0.f, 0.f, 0.f, 0.f);
    float4 a1 = make_float4(0.f, 0.f, 0.f, 0.f);
    for (int e = beg; e < end; e++) {
        int s = __ldg(&g_esrc[e]);
        float w = __ldg(&g_ew[e]);
        const float4* src = (const float4*)&g_R[(size_t)s * 256];
        float4 v0 = src[l], v1 = src[l + 32];
        a0.x += w * v0.x; a0.y += w * v0.y; a0.z += w * v0.z; a0.w += w * v0.w;
        a1.x += w * v1.x; a1.y += w * v1.y; a1.z += w * v1.z; a1.w += w * v1.w;
    }
    float4* dst = (float4*)&g_Rn[(size_t)warp * 256];
    float4 r0 = dst[l], r1 = dst[l + 32];
    r0.x += a0.x; r0.y += a0.y; r0.z += a0.z; r0.w += a0.w;
    r1.x += a1.x; r1.y += a1.y; r1.z += a1.z; r1.w += a1.w;
    dst[l] = r0; dst[l + 32] = r1;
}

// ---------------- blend + LayerNorm + split write + readout accumulate --------
__global__ void blend_ln(const float* __restrict__ alpha_p,
                         const float* __restrict__ gamma, const float* __restrict__ beta,
                         const float* __restrict__ Wr, const float* __restrict__ br,
                         const float* __restrict__ wgt, int sidx,
                         float* __restrict__ out, int M)
{
    int gw = (blockIdx.x * blockDim.x + threadIdx.x) >> 5;
    int l = threadIdx.x & 31;
    if (gw >= M) return;
    float al = alpha_p[0];
    size_t base = (size_t)gw * 256;
    float h[8]; float sum = 0.f, sq = 0.f;
    #pragma unroll
    for (int j = 0; j < 8; j++) {
        int idx = j * 32 + l;
        float v = al * g_Rn[base + idx] + (1.f - al) * g_R[base + idx];
        h[j] = v; sum += v; sq += v * v;
    }
    #pragma unroll
    for (int o = 16; o > 0; o >>= 1) {
        sum += __shfl_xor_sync(0xffffffffu, sum, o);
        sq  += __shfl_xor_sync(0xffffffffu, sq, o);
    }
    float mu  = sum * (1.f / 256.f);
    float var = sq * (1.f / 256.f) - mu * mu;
    float rstd = rsqrtf(var + 1e-5f);
    const float* wr = Wr + sidx * 256;
    float dot = 0.f;
    #pragma unroll
    for (int j = 0; j < 8; j++) {
        int idx = j * 32 + l;
        float y = (h[j] - mu) * rstd * gamma[idx] + beta[idx];
        g_R[base + idx] = y;
        split_store(y, g_Rh, g_Rl, base + idx);
        dot += y * wr[idx];
    }
    #pragma unroll
    for (int o = 16; o > 0; o >>= 1) dot += __shfl_xor_sync(0xffffffffu, dot, o);
    if (l == 0) out[gw] += wgt[sidx] * (dot + br[sidx]);
}

__global__ void readout0(const float* __restrict__ Wr, const float* __restrict__ br,
                         const float* __restrict__ wgt, float* __restrict__ out, int M)
{
    int gw = (blockIdx.x * blockDim.x + threadIdx.x) >> 5;
    int l = threadIdx.x & 31;
    if (gw >= M) return;
    float dot = 0.f;
    #pragma unroll
    for (int j = 0; j < 8; j++) {
        int idx = j * 32 + l;
        dot += g_R[(size_t)gw * 256 + idx] * Wr[idx];
    }
    #pragma unroll
    for (int o = 16; o > 0; o >>= 1) dot += __shfl_xor_sync(0xffffffffu, dot, o);
    if (l == 0) out[gw] = wgt[0] * (dot + br[0]);
}

// ---------------- host orchestration ------------------------------------------
extern "C" void kernel_launch(void* const* d_in, const int* in_sizes, int n_in,
                              void* d_out, int out_size)
{
    const float* x     = (const float*)d_in[0];
    const int*   ei    = (const int*)  d_in[1];
    const float* W1    = (const float*)d_in[2];
    const float* b1    = (const float*)d_in[3];
    const float* Wq    = (const float*)d_in[4];
    const float* bq    = (const float*)d_in[5];
    const float* Wk    = (const float*)d_in[6];
    const float* bk    = (const float*)d_in[7];
    const float* gamma = (const float*)d_in[8];
    const float* beta  = (const float*)d_in[9];
    const float* alpha = (const float*)d_in[10];
    const float* Wr    = (const float*)d_in[11];
    const float* br    = (const float*)d_in[12];
    const float* wgt   = (const float*)d_in[13];
    float* out = (float*)d_out;

    const int N = in_sizes[0] / FIN;
    const int E = in_sizes[1] / 2;
    const int* erow = ei;
    const int* ecol = ei + E;

    static bool attr_set = false;
    if (!attr_set) {
        cudaFuncSetAttribute(mma_gemm<0>, cudaFuncAttributeMaxDynamicSharedMemorySize, 2 * STAGE_BYTES);
        cudaFuncSetAttribute(mma_gemm<1>, cudaFuncAttributeMaxDynamicSharedMemorySize, 2 * STAGE_BYTES);
        cudaFuncSetAttribute(mma_gemm<2>, cudaFuncAttributeMaxDynamicSharedMemorySize, 2 * STAGE_BYTES);
        attr_set = true;
    }

    static float *pR = 0, *pRn = 0, *pKv = 0, *pStats = 0;
    static bf16 *pRh = 0, *pRl = 0, *pRTh = 0, *pRTl = 0, *pkTh = 0, *pkTl = 0,
                *pqkh = 0, *pqkl = 0, *pWTh = 0, *pWTl = 0, *pkvTh = 0, *pkvTl = 0;
    if (!pR) {
        cudaGetSymbolAddress((void**)&pR,    g_R);
        cudaGetSymbolAddress((void**)&pRn,   g_Rn);
        cudaGetSymbolAddress((void**)&pKv,   g_kv);
        cudaGetSymbolAddress((void**)&pStats,g_stats);
        cudaGetSymbolAddress((void**)&pRh,   g_Rh);
        cudaGetSymbolAddress((void**)&pRl,   g_Rl);
        cudaGetSymbolAddress((void**)&pRTh,  g_RTh);
        cudaGetSymbolAddress((void**)&pRTl,  g_RTl);
        cudaGetSymbolAddress((void**)&pkTh,  g_kTh);
        cudaGetSymbolAddress((void**)&pkTl,  g_kTl);
        cudaGetSymbolAddress((void**)&pqkh,  g_qkh);
        cudaGetSymbolAddress((void**)&pqkl,  g_qkl);
        cudaGetSymbolAddress((void**)&pWTh,  g_WqkTh);
        cudaGetSymbolAddress((void**)&pWTl,  g_WqkTl);
        cudaGetSymbolAddress((void**)&pkvTh, g_kvTh);
        cudaGetSymbolAddress((void**)&pkvTl, g_kvTl);
    }

    const int mtiles = (N + 127) / 128;
    const int tgrid = (N * 32 + 255) / 256;
    const int nb1 = (N + 1023) / 1024;

    // ---- CSR build (once per call; amortized over 3 iterations) ----
    zero_i2     <<<(N + 255) / 256, 256>>>(N);
    cnt_deg     <<<(E + 255) / 256, 256>>>(ecol, E);
    invsqrt_k   <<<(N + 255) / 256, 256>>>(N);
    scan1       <<<nb1, 256>>>(N);
    scan2       <<<1, 128>>>(nb1);
    scan3       <<<(N + 255) / 256, 256>>>(N, E);
    edge_scatter<<<(E + 255) / 256, 256>>>(erow, ecol, E);

    build_wqkT<<<(2 * H * H + 255) / 256, 256>>>(Wq, Wk);

    // R = relu(x @ W1 + b1), with split-bf16 side output
    {
        dim3 g((H + 127) / 128, (N + 127) / 128);
        sgemm_relu<<<g, 256>>>(x, FIN, W1, H, b1, pR, H, N, FIN, pRh, pRl);
    }

    readout0<<<tgrid, 256>>>(Wr, br, wgt, out, N);

    for (int it = 0; it < 3; it++) {
        // [q|k] = R @ [Wq|Wk] + bias
        mma_gemm<0><<<dim3(mtiles, 8, 1), 256, 2 * STAGE_BYTES>>>(
            pRh, pRl, 256, pWTh, pWTl, 256, N, 256, 256,
            bq, bk, nullptr, pqkh, pqkl);

        zero_k<<<(H * H + 255) / 256, 256>>>(pKv, H * H);
        zero_k<<<3, 256>>>(pStats, 2 + 2 * H);

        reduce_stats<<<(N + 127) / 128, 256>>>(N);

        // transposed split planes: k^T and v^T(=R^T)
        {
            dim3 g((N + 31) / 32, 8), b(32, 8);
            transpose_bf16<<<g, b>>>(pqkh + 256, pkTh, N, 512, N);
            transpose_bf16<<<g, b>>>(pqkl + 256, pkTl, N, 512, N);
            transpose_bf16<<<g, b>>>(pRh, pRTh, N, 256, N);
            transpose_bf16<<<g, b>>>(pRl, pRTl, N, 256, N);
        }

        // kv = k^T @ v  (split-K over N, atomic fp32 merge)
        {
            int zchunks = (N + 511) / 512;
            mma_gemm<2><<<dim3(2, 4, zchunks), 256, 2 * STAGE_BYTES>>>(
                pkTh, pkTl, N, pRTh, pRTl, N, 256, N, 512,
                nullptr, nullptr, nullptr, nullptr, nullptr);
        }

        finalize_s<<<1, 1>>>();
        den_kernel<<<tgrid, 256>>>(N, (float)N);
        build_kvT<<<(H * H + 255) / 256, 256>>>();

        // Rn = (q @ kv * s + vsum) * invden
        mma_gemm<1><<<dim3(mtiles, 4, 1), 256, 2 * STAGE_BYTES>>>(
            pqkh, pqkl, 512, pkvTh, pkvTl, 256, N, 256, 256,
            nullptr, nullptr, pRn, nullptr, nullptr);

        // Rn += GCN(R)  via CSR gather (no atomics)
        gcn_gather<<<(N + 7) / 8, 256>>>(N);

        // R = LN(alpha*Rn + (1-alpha)*R); readout accumulate
        blend_ln<<<tgrid, 256>>>(alpha, gamma, beta, Wr, br, wgt, it + 1, out, N);
    }
}

// round 5
// speedup vs baseline: 2.3835x; 1.2443x over previous
#include <cuda_runtime.h>
#include <cuda_bf16.h>
#include <math.h>
#include <stdint.h>

#define H 256
#define FIN 58
#define N_MAX 100000
#define E_MAX 3200000

typedef __nv_bfloat16 bf16;

// ---------------- scratch (device globals; no allocation allowed) ------------
__device__ float g_R  [(size_t)N_MAX * H];
__device__ float g_Rn [(size_t)N_MAX * H];
__device__ bf16  g_Rh [(size_t)N_MAX * H];
__device__ bf16  g_Rl [(size_t)N_MAX * H];
__device__ bf16  g_RTh[(size_t)H * N_MAX];
__device__ bf16  g_RTl[(size_t)H * N_MAX];
__device__ bf16  g_kTh[(size_t)H * N_MAX];
__device__ bf16  g_kTl[(size_t)H * N_MAX];
__device__ bf16  g_qkh[(size_t)N_MAX * 2 * H];   // only q half used now
__device__ bf16  g_qkl[(size_t)N_MAX * 2 * H];
__device__ bf16  g_WqkTh[2 * H * H];
__device__ bf16  g_WqkTl[2 * H * H];
__device__ bf16  g_kvTh[H * H];
__device__ bf16  g_kvTl[H * H];
__device__ float g_kv [H * H];
__device__ float g_dinv[N_MAX];
__device__ float g_invden[N_MAX];
__device__ float g_stats[2 + 2 * H];             // [q2, k2, ksum[256], vsum[256]]
__device__ float g_s[1];
// CSR structures
__device__ int   g_degi[N_MAX];
__device__ int   g_cur [N_MAX];
__device__ int   g_off [N_MAX + 1];
__device__ int   g_bsum[128];
__device__ int   g_esrc[E_MAX];
__device__ float g_ew  [E_MAX];

// ---------------- PTX helpers --------------------------------------------------
__device__ __forceinline__ uint32_t smem_u32(const void* p) {
    uint32_t a;
    asm("{ .reg .u64 t; cvta.to.shared.u64 t, %1; cvt.u32.u64 %0, t; }" : "=r"(a) : "l"(p));
    return a;
}
__device__ __forceinline__ void ldsm4(uint32_t* r, uint32_t addr) {
    asm volatile("ldmatrix.sync.aligned.m8n8.x4.shared.b16 {%0,%1,%2,%3}, [%4];"
                 : "=r"(r[0]), "=r"(r[1]), "=r"(r[2]), "=r"(r[3]) : "r"(addr));
}
__device__ __forceinline__ void mma16816(float* c, const uint32_t* a, uint32_t b0, uint32_t b1) {
    asm volatile("mma.sync.aligned.m16n8k16.row.col.f32.bf16.bf16.f32 "
                 "{%0,%1,%2,%3}, {%4,%5,%6,%7}, {%8,%9}, {%0,%1,%2,%3};"
                 : "+f"(c[0]), "+f"(c[1]), "+f"(c[2]), "+f"(c[3])
                 : "r"(a[0]), "r"(a[1]), "r"(a[2]), "r"(a[3]), "r"(b0), "r"(b1));
}
__device__ __forceinline__ void cpa16(uint32_t dst, const void* src, bool pred) {
    int sz = pred ? 16 : 0;
    asm volatile("cp.async.cg.shared.global [%0], [%1], 16, %2;"
                 :: "r"(dst), "l"(src), "r"(sz));
}
#define CP_COMMIT() asm volatile("cp.async.commit_group;" ::: "memory")
#define SW128(o) ((o) ^ (((o) >> 3) & 0x70))

// ---------------- tiny utility kernels ---------------------------------------
__global__ void zero_k(float* p, int n) {
    int i = blockIdx.x * blockDim.x + threadIdx.x;
    if (i < n) p[i] = 0.f;
}
__global__ void zero_i2(int n) {
    int i = blockIdx.x * blockDim.x + threadIdx.x;
    if (i < n) { g_degi[i] = 0; g_cur[i] = 0; }
}
__global__ void cnt_deg(const int* __restrict__ col, int E) {
    int i = blockIdx.x * blockDim.x + threadIdx.x;
    if (i < E) atomicAdd(&g_degi[col[i]], 1);
}
__global__ void invsqrt_k(int n) {
    int i = blockIdx.x * blockDim.x + threadIdx.x;
    if (i < n) {
        int d = g_degi[i];
        g_dinv[i] = (d > 0) ? rsqrtf((float)d) : 0.f;
    }
}
// ---- 2-level exclusive scan of g_degi -> g_off -------------------------------
__global__ __launch_bounds__(256) void scan1(int n) {
    __shared__ int s[256];
    int b = blockIdx.x, t = threadIdx.x;
    int base = b * 1024 + t * 4;
    int v0 = 0, v1 = 0, v2 = 0, v3 = 0;
    if (base + 0 < n) v0 = g_degi[base + 0];
    if (base + 1 < n) v1 = g_degi[base + 1];
    if (base + 2 < n) v2 = g_degi[base + 2];
    if (base + 3 < n) v3 = g_degi[base + 3];
    int tsum = v0 + v1 + v2 + v3;
    s[t] = tsum;
    __syncthreads();
    for (int o = 1; o < 256; o <<= 1) {
        int x = 0;
        if (t >= o) x = s[t - o];
        __syncthreads();
        s[t] += x;
        __syncthreads();
    }
    int ex = s[t] - tsum;
    if (base + 0 < n) g_off[base + 0] = ex;
    if (base + 1 < n) g_off[base + 1] = ex + v0;
    if (base + 2 < n) g_off[base + 2] = ex + v0 + v1;
    if (base + 3 < n) g_off[base + 3] = ex + v0 + v1 + v2;
    if (t == 255) g_bsum[b] = s[255];
}
__global__ void scan2(int nb) {
    __shared__ int s[128];
    int t = threadIdx.x;
    int v = (t < nb) ? g_bsum[t] : 0;
    s[t] = v;
    __syncthreads();
    for (int o = 1; o < 128; o <<= 1) {
        int x = 0;
        if (t >= o) x = s[t - o];
        __syncthreads();
        s[t] += x;
        __syncthreads();
    }
    g_bsum[t] = s[t] - v;
}
__global__ void scan3(int n, int E) {
    int i = blockIdx.x * blockDim.x + threadIdx.x;
    if (i < n) g_off[i] += g_bsum[i >> 10];
    if (i == 0) g_off[n] = E;
}
__global__ void edge_scatter(const int* __restrict__ erow, const int* __restrict__ ecol, int E) {
    int e = blockIdx.x * blockDim.x + threadIdx.x;
    if (e >= E) return;
    int c = ecol[e], r = erow[e];
    int pos = g_off[c] + atomicAdd(&g_cur[c], 1);
    g_esrc[pos] = r;
    g_ew[pos] = g_dinv[r] * g_dinv[c];
}

__device__ __forceinline__ void split_store(float v, bf16* ph, bf16* pl, size_t idx) {
    bf16 h = __float2bfloat16(v);
    ph[idx] = h;
    pl[idx] = __float2bfloat16(v - __bfloat162float(h));
}
__global__ void build_wqkT(const float* __restrict__ Wq, const float* __restrict__ Wk) {
    int idx = blockIdx.x * blockDim.x + threadIdx.x;
    if (idx >= 2 * H * H) return;
    int n = idx >> 8, k = idx & 255;
    float w = (n < H) ? Wq[k * H + n] : Wk[k * H + (n - H)];
    split_store(w, g_WqkTh, g_WqkTl, idx);
}
__global__ void build_kvT() {
    int idx = blockIdx.x * blockDim.x + threadIdx.x;
    if (idx >= H * H) return;
    int d = idx >> 8, m = idx & 255;
    split_store(g_kv[m * H + d], g_kvTh, g_kvTl, idx);
}
// merged hi+lo tiled transpose: out[c][r] = in[r][c]; in rows x 256 cols
__global__ void transpose2_bf16(const bf16* __restrict__ ih, const bf16* __restrict__ il,
                                bf16* __restrict__ oh, bf16* __restrict__ ol,
                                int rows, int istride, int ostride) {
    __shared__ bf16 th[32][33], tl[32][33];
    int r0 = blockIdx.x * 32, c0 = blockIdx.y * 32;
    for (int i = threadIdx.y; i < 32; i += 8) {
        int r = r0 + i, c = c0 + threadIdx.x;
        bf16 zh = __float2bfloat16(0.f);
        th[i][threadIdx.x] = (r < rows) ? ih[(size_t)r * istride + c] : zh;
        tl[i][threadIdx.x] = (r < rows) ? il[(size_t)r * istride + c] : zh;
    }
    __syncthreads();
    for (int i = threadIdx.y; i < 32; i += 8) {
        int oc = r0 + threadIdx.x, orow = c0 + i;
        if (oc < rows) {
            oh[(size_t)orow * ostride + oc] = th[threadIdx.x][i];
            ol[(size_t)orow * ostride + oc] = tl[threadIdx.x][i];
        }
    }
}

// ---------------- fp32 SGEMM for x@W1 (K=58) with relu + split epilogue -------
__global__ __launch_bounds__(256) void sgemm_relu(
    const float* __restrict__ A, int lda,
    const float* __restrict__ B, int ldb,
    const float* __restrict__ bias,
    float* __restrict__ C, int ldc,
    int M, int K,
    bf16* __restrict__ Ch, bf16* __restrict__ Cl)
{
    __shared__ float As[8][128];
    __shared__ float Bs[8][128];
    const int tid = threadIdx.x;
    const int row0 = blockIdx.y * 128, col0 = blockIdx.x * 128;
    const int tr = tid >> 4, tc = tid & 15;
    const int ar = tid >> 1, as_ = (tid & 1) * 4;
    const int bkr = tid >> 5, bc = (tid & 31) * 4;

    float acc[8][8] = {};
    const int ksteps = (K + 7) / 8;
    for (int kt = 0; kt < ksteps; kt++) {
        int k0 = kt * 8;
        {
            int r = row0 + ar;
            #pragma unroll
            for (int j = 0; j < 4; j++) {
                int k = k0 + as_ + j;
                As[as_ + j][ar] = (r < M && k < K) ? A[(size_t)r * lda + k] : 0.f;
            }
        }
        {
            int k = k0 + bkr;
            float4 v = make_float4(0.f, 0.f, 0.f, 0.f);
            if (k < K) v = *(const float4*)&B[(size_t)k * ldb + col0 + bc];
            *(float4*)&Bs[bkr][bc] = v;
        }
        __syncthreads();
        #pragma unroll
        for (int kk = 0; kk < 8; kk++) {
            float a[8], b[8];
            *(float4*)&a[0] = *(const float4*)&As[kk][tr * 8];
            *(float4*)&a[4] = *(const float4*)&As[kk][tr * 8 + 4];
            *(float4*)&b[0] = *(const float4*)&Bs[kk][tc * 8];
            *(float4*)&b[4] = *(const float4*)&Bs[kk][tc * 8 + 4];
            #pragma unroll
            for (int i = 0; i < 8; i++)
                #pragma unroll
                for (int j = 0; j < 8; j++)
                    acc[i][j] += a[i] * b[j];
        }
        __syncthreads();
    }

    float bb[8];
    #pragma unroll
    for (int j = 0; j < 8; j++) bb[j] = bias[col0 + tc * 8 + j];
    #pragma unroll
    for (int i = 0; i < 8; i++) {
        int r = row0 + tr * 8 + i;
        if (r >= M) continue;
        #pragma unroll
        for (int j = 0; j < 8; j++) {
            int c = col0 + tc * 8 + j;
            float val = fmaxf(acc[i][j] + bb[j], 0.f);
            size_t idx = (size_t)r * ldc + c;
            C[idx] = val;
            split_store(val, Ch, Cl, idx);
        }
    }
}

// ---------------- mma.sync split-bf16 GEMM, 2-stage cp.async pipeline ---------
// C[m,n] = sum_k A[m,k]*B[n,k]; BM=128 BN=64 BK=64; 8 warps 4x2; warp 32x32.
// EPI 0: qk (q blocks: +bias, split planes, q2 atomic;
//            k blocks: +bias, kT planes via smem transpose, k2+ksum atomics)
// EPI 1: attn  EPI 2: kv (atomic fp32)
#define STAGE_BYTES 49152
template <int EPI>
__global__ __launch_bounds__(256, 2) void mma_gemm(
    const bf16* __restrict__ Ah_, const bf16* __restrict__ Al_, int lda,
    const bf16* __restrict__ Bh_, const bf16* __restrict__ Bl_, int ldb,
    int Mrows, int Ktot, int kchunk,
    const float* __restrict__ e0, const float* __restrict__ e1,
    float* __restrict__ outf, bf16* __restrict__ oh, bf16* __restrict__ ol,
    bf16* __restrict__ okTh, bf16* __restrict__ okTl)
{
    extern __shared__ char smem[];
    const int tid = threadIdx.x, wid = tid >> 5, lane = tid & 31;
    const int wm = (wid & 3) * 32;
    const int wn = (wid >> 2) * 32;
    const int row0 = blockIdx.x * 128;
    const int ncol0 = blockIdx.y * 64;
    const int k0 = blockIdx.z * kchunk;
    int kend = k0 + kchunk; if (kend > Ktot) kend = Ktot;
    const uint32_t sbase = smem_u32(smem);

    auto fill = [&](int stage, int ks) {
        uint32_t sa = sbase + stage * STAGE_BYTES;
        #pragma unroll
        for (int it = 0; it < 4; it++) {
            int ch = tid + it * 256;
            int r = ch >> 3, c8 = ch & 7;
            int g = row0 + r;
            int kb = ks + c8 * 8;
            uint32_t off = SW128((uint32_t)(r * 128 + c8 * 16));
            bool p = (g < Mrows) && (kb + 8 <= kend);
            const bf16* ph = p ? &Ah_[(size_t)g * lda + kb] : Ah_;
            const bf16* pl = p ? &Al_[(size_t)g * lda + kb] : Al_;
            cpa16(sa + off, ph, p);
            cpa16(sa + 16384 + off, pl, p);
        }
        #pragma unroll
        for (int it = 0; it < 2; it++) {
            int ch = tid + it * 256;
            int r = ch >> 3, c8 = ch & 7;
            int gn = ncol0 + r;
            int kb = ks + c8 * 8;
            uint32_t off = SW128((uint32_t)(r * 128 + c8 * 16));
            bool p = (kb + 8 <= kend);
            const bf16* ph = p ? &Bh_[(size_t)gn * ldb + kb] : Bh_;
            const bf16* pl = p ? &Bl_[(size_t)gn * ldb + kb] : Bl_;
            cpa16(sa + 32768 + off, ph, p);
            cpa16(sa + 40960 + off, pl, p);
        }
    };

    float acc[2][4][4] = {};
    int stage = 0;
    fill(0, k0);
    CP_COMMIT();

    for (int ks = k0; ks < kend; ks += 64) {
        int nxt = ks + 64;
        if (nxt < kend) {
            fill(stage ^ 1, nxt);
            CP_COMMIT();
            asm volatile("cp.async.wait_group 1;" ::: "memory");
        } else {
            asm volatile("cp.async.wait_group 0;" ::: "memory");
        }
        __syncthreads();

        uint32_t base = sbase + stage * STAGE_BYTES;
        #pragma unroll
        for (int kc = 0; kc < 4; kc++) {
            uint32_t ah[2][4], al[2][4], bh[2][4], bl[2][4];
            #pragma unroll
            for (int mt = 0; mt < 2; mt++) {
                uint32_t off = SW128((uint32_t)((wm + mt * 16 + (lane & 15)) * 128 +
                                                (kc * 16 + (lane >> 4) * 8) * 2));
                ldsm4(ah[mt], base + off);
                ldsm4(al[mt], base + 16384 + off);
            }
            #pragma unroll
            for (int ntp = 0; ntp < 2; ntp++) {
                uint32_t off = SW128((uint32_t)((wn + ntp * 16 + ((lane >> 4) & 1) * 8 + (lane & 7)) * 128 +
                                                (kc * 16 + ((lane >> 3) & 1) * 8) * 2));
                ldsm4(bh[ntp], base + 32768 + off);
                ldsm4(bl[ntp], base + 40960 + off);
            }
            #pragma unroll
            for (int mt = 0; mt < 2; mt++)
                #pragma unroll
                for (int nt = 0; nt < 4; nt++) {
                    uint32_t b0h = bh[nt >> 1][(nt & 1) * 2], b1h = bh[nt >> 1][(nt & 1) * 2 + 1];
                    uint32_t b0l = bl[nt >> 1][(nt & 1) * 2], b1l = bl[nt >> 1][(nt & 1) * 2 + 1];
                    mma16816(acc[mt][nt], ah[mt], b0h, b1h);
                    mma16816(acc[mt][nt], ah[mt], b0l, b1l);
                    mma16816(acc[mt][nt], al[mt], b0h, b1h);
                }
        }
        __syncthreads();
        stage ^= 1;
    }

    // ---- epilogues -----------------------------------------------------------
    if (EPI == 1) {
        float s_val = g_s[0];
        #pragma unroll
        for (int mt = 0; mt < 2; mt++)
            #pragma unroll
            for (int rg = 0; rg < 4; rg++) {
                int r = row0 + wm + mt * 16 + (lane >> 2) + ((rg >> 1) & 1) * 8;
                if (r >= Mrows) continue;
                #pragma unroll
                for (int nt = 0; nt < 4; nt++) {
                    int c = ncol0 + wn + nt * 8 + (lane & 3) * 2 + (rg & 1);
                    float v = (acc[mt][nt][rg] * s_val + g_stats[2 + H + c]) * g_invden[r];
                    outf[(size_t)r * H + c] = v;
                }
            }
    } else if (EPI == 2) {
        #pragma unroll
        for (int mt = 0; mt < 2; mt++)
            #pragma unroll
            for (int rg = 0; rg < 4; rg++) {
                int r = row0 + wm + mt * 16 + (lane >> 2) + ((rg >> 1) & 1) * 8;
                if (r >= Mrows) continue;
                #pragma unroll
                for (int nt = 0; nt < 4; nt++) {
                    int c = ncol0 + wn + nt * 8 + (lane & 3) * 2 + (rg & 1);
                    atomicAdd(&g_kv[(size_t)r * H + c], acc[mt][nt][rg]);
                }
            }
    } else {
        // EPI 0 — qk projection
        const bool is_k = (ncol0 >= 256);
        float* red_sm = (float*)(smem + 35328);
        float sq_part = 0.f;

        if (!is_k) {
            #pragma unroll
            for (int mt = 0; mt < 2; mt++)
                #pragma unroll
                for (int rg = 0; rg < 4; rg++) {
                    int r = row0 + wm + mt * 16 + (lane >> 2) + ((rg >> 1) & 1) * 8;
                    #pragma unroll
                    for (int nt = 0; nt < 4; nt++) {
                        int c = ncol0 + wn + nt * 8 + (lane & 3) * 2 + (rg & 1);
                        float v = 0.f;
                        if (r < Mrows) {
                            v = acc[mt][nt][rg] + e0[c];
                            split_store(v, oh, ol, (size_t)r * 512 + c);
                        }
                        sq_part += v * v;
                    }
                }
        } else {
            bf16* sTh = (bf16*)smem;                 // [64][136]
            bf16* sTl = (bf16*)(smem + 17408);
            float* ksum_sm = (float*)(smem + 34816); // [64]
            if (tid < 64) ksum_sm[tid] = 0.f;
            float colp[4][2];
            #pragma unroll
            for (int nt = 0; nt < 4; nt++) { colp[nt][0] = 0.f; colp[nt][1] = 0.f; }

            #pragma unroll
            for (int mt = 0; mt < 2; mt++)
                #pragma unroll
                for (int rg = 0; rg < 4; rg++) {
                    int rl = wm + mt * 16 + (lane >> 2) + ((rg >> 1) & 1) * 8;
                    int r = row0 + rl;
                    #pragma unroll
                    for (int nt = 0; nt < 4; nt++) {
                        int cl = wn + nt * 8 + (lane & 3) * 2 + (rg & 1);
                        float v = 0.f;
                        if (r < Mrows) v = acc[mt][nt][rg] + e1[ncol0 - 256 + cl];
                        sq_part += v * v;
                        colp[nt][rg & 1] += v;
                        bf16 h = __float2bfloat16(v);
                        sTh[cl * 136 + rl] = h;
                        sTl[cl * 136 + rl] = __float2bfloat16(v - __bfloat162float(h));
                    }
                }
            // reduce colp over lanes differing in (lane>>2)
            #pragma unroll
            for (int nt = 0; nt < 4; nt++)
                #pragma unroll
                for (int par = 0; par < 2; par++) {
                    float v = colp[nt][par];
                    v += __shfl_xor_sync(0xffffffffu, v, 4);
                    v += __shfl_xor_sync(0xffffffffu, v, 8);
                    v += __shfl_xor_sync(0xffffffffu, v, 16);
                    colp[nt][par] = v;
                }
            __syncthreads();   // ksum_sm zeroed + sT writes visible
            if ((lane >> 2) == 0) {
                #pragma unroll
                for (int nt = 0; nt < 4; nt++)
                    #pragma unroll
                    for (int par = 0; par < 2; par++) {
                        int cl = wn + nt * 8 + (lane & 3) * 2 + par;
                        atomicAdd(&ksum_sm[cl], colp[nt][par]);
                    }
            }
            __syncthreads();
            if (tid < 64)
                atomicAdd(&g_stats[2 + (ncol0 - 256) + tid], ksum_sm[tid]);
            // copy kT tiles out: 64 k-rows x 128 node-cols
            {
                int rowc = tid >> 2, quarter = tid & 3;
                int gk = ncol0 - 256 + rowc;
                size_t gbase = (size_t)gk * lda /*unused*/;
                (void)gbase;
                size_t gb = (size_t)gk * (size_t)Mrows + row0;
                // note: kT leading dim is Mrows? NO — leading dim is Ktot of kv gemm = N nodes.
                // kT layout: okTh[k * Nnodes + node]; Nnodes == Mrows here.
                if (row0 + 128 <= Mrows) {
                    #pragma unroll
                    for (int j = 0; j < 4; j++) {
                        int rr = quarter * 32 + j * 8;
                        int4 vh = *(int4*)&sTh[rowc * 136 + rr];
                        int4 vl = *(int4*)&sTl[rowc * 136 + rr];
                        *(int4*)&okTh[gb + rr] = vh;
                        *(int4*)&okTl[gb + rr] = vl;
                    }
                } else {
                    for (int rr = quarter * 32; rr < quarter * 32 + 32; rr++) {
                        if (row0 + rr < Mrows) {
                            okTh[gb + rr] = sTh[rowc * 136 + rr];
                            okTl[gb + rr] = sTl[rowc * 136 + rr];
                        }
                    }
                }
            }
        }
        // block-reduce sq_part -> q2 or k2
        #pragma unroll
        for (int o = 16; o > 0; o >>= 1) sq_part += __shfl_xor_sync(0xffffffffu, sq_part, o);
        if (lane == 0) red_sm[wid] = sq_part;
        __syncthreads();
        if (tid == 0) {
            float t = 0.f;
            #pragma unroll
            for (int w = 0; w < 8; w++) t += red_sm[w];
            atomicAdd(&g_stats[is_k ? 1 : 0], t);
        }
    }
}

// ---------------- vsum: colsum of R ------------------------------------------
__global__ __launch_bounds__(256) void vsum_k(int M) {
    int t = threadIdx.x;
    int r0 = blockIdx.x * 128;
    int rend = r0 + 128; if (rend > M) rend = M;
    float vs = 0.f;
    for (int r = r0; r < rend; r++) vs += g_R[(size_t)r * 256 + t];
    atomicAdd(&g_stats[2 + 256 + t], vs);
}

__global__ void finalize_s() {
    g_s[0] = rsqrtf(g_stats[0]) * rsqrtf(g_stats[1]);
}

__global__ void den_kernel(int M, float fN) {
    int gw = (blockIdx.x * blockDim.x + threadIdx.x) >> 5;
    int l = threadIdx.x & 31;
    if (gw >= M) return;
    size_t base = (size_t)gw * 512;
    float sum = 0.f;
    #pragma unroll
    for (int j = 0; j < 8; j++) {
        int idx = j * 32 + l;
        float qv = __bfloat162float(g_qkh[base + idx]) + __bfloat162float(g_qkl[base + idx]);
        sum += qv * g_stats[2 + idx];
    }
    #pragma unroll
    for (int o = 16; o > 0; o >>= 1) sum += __shfl_xor_sync(0xffffffffu, sum, o);
    if (l == 0) g_invden[gw] = 1.0f / (g_s[0] * sum + fN);
}

// ---------------- GCN gather: Rn[c] += sum_e w[e] * R[src[e]] -----------------
// One warp per destination node; 128 dims per pass (L2 residency); unroll 2.
__global__ __launch_bounds__(256) void gcn_gather(int Nn, int dimoff) {
    int warp = (blockIdx.x * blockDim.x + threadIdx.x) >> 5;
    if (warp >= Nn) return;
    int l = threadIdx.x & 31;
    int beg = g_off[warp], end = g_off[warp + 1];
    if (beg == end) return;
    float4 a = make_float4(0.f, 0.f, 0.f, 0.f);
    const float* Rbase = &g_R[(size_t)dimoff + l * 4];
    int e = beg;
    for (; e + 2 <= end; e += 2) {
        int s0 = __ldg(&g_esrc[e]);
        int s1 = __ldg(&g_esrc[e + 1]);
        float w0 = __ldg(&g_ew[e]);
        float w1 = __ldg(&g_ew[e + 1]);
        float4 v0 = *(const float4*)&Rbase[(size_t)s0 * 256];
        float4 v1 = *(const float4*)&Rbase[(size_t)s1 * 256];
        a.x += w0 * v0.x + w1 * v1.x;
        a.y += w0 * v0.y + w1 * v1.y;
        a.z += w0 * v0.z + w1 * v1.z;
        a.w += w0 * v0.w + w1 * v1.w;
    }
    if (e < end) {
        int s0 = __ldg(&g_esrc[e]);
        float w0 = __ldg(&g_ew[e]);
        float4 v0 = *(const float4*)&Rbase[(size_t)s0 * 256];
        a.x += w0 * v0.x; a.y += w0 * v0.y; a.z += w0 * v0.z; a.w += w0 * v0.w;
    }
    float4* dst = (float4*)&g_Rn[(size_t)warp * 256 + dimoff];
    float4 r = dst[l];
    r.x += a.x; r.y += a.y; r.z += a.z; r.w += a.w;
    dst[l] = r;
}

// ---------------- blend + LayerNorm + split write + readout accumulate --------
__global__ void blend_ln(const float* __restrict__ alpha_p,
                         const float* __restrict__ gamma, const float* __restrict__ beta,
                         const float* __restrict__ Wr, const float* __restrict__ br,
                         const float* __restrict__ wgt, int sidx,
                         float* __restrict__ out, int M)
{
    int gw = (blockIdx.x * blockDim.x + threadIdx.x) >> 5;
    int l = threadIdx.x & 31;
    if (gw >= M) return;
    float al = alpha_p[0];
    size_t base = (size_t)gw * 256;
    float h[8]; float sum = 0.f, sq = 0.f;
    #pragma unroll
    for (int j = 0; j < 8; j++) {
        int idx = j * 32 + l;
        float v = al * g_Rn[base + idx] + (1.f - al) * g_R[base + idx];
        h[j] = v; sum += v; sq += v * v;
    }
    #pragma unroll
    for (int o = 16; o > 0; o >>= 1) {
        sum += __shfl_xor_sync(0xffffffffu, sum, o);
        sq  += __shfl_xor_sync(0xffffffffu, sq, o);
    }
    float mu  = sum * (1.f / 256.f);
    float var = sq * (1.f / 256.f) - mu * mu;
    float rstd = rsqrtf(var + 1e-5f);
    const float* wr = Wr + sidx * 256;
    float dot = 0.f;
    #pragma unroll
    for (int j = 0; j < 8; j++) {
        int idx = j * 32 + l;
        float y = (h[j] - mu) * rstd * gamma[idx] + beta[idx];
        g_R[base + idx] = y;
        split_store(y, g_Rh, g_Rl, base + idx);
        dot += y * wr[idx];
    }
    #pragma unroll
    for (int o = 16; o > 0; o >>= 1) dot += __shfl_xor_sync(0xffffffffu, dot, o);
    if (l == 0) out[gw] += wgt[sidx] * (dot + br[sidx]);
}

__global__ void readout0(const float* __restrict__ Wr, const float* __restrict__ br,
                         const float* __restrict__ wgt, float* __restrict__ out, int M)
{
    int gw = (blockIdx.x * blockDim.x + threadIdx.x) >> 5;
    int l = threadIdx.x & 31;
    if (gw >= M) return;
    float dot = 0.f;
    #pragma unroll
    for (int j = 0; j < 8; j++) {
        int idx = j * 32 + l;
        dot += g_R[(size_t)gw * 256 + idx] * Wr[idx];
    }
    #pragma unroll
    for (int o = 16; o > 0; o >>= 1) dot += __shfl_xor_sync(0xffffffffu, dot, o);
    if (l == 0) out[gw] = wgt[0] * (dot + br[0]);
}

// ---------------- host orchestration ------------------------------------------
extern "C" void kernel_launch(void* const* d_in, const int* in_sizes, int n_in,
                              void* d_out, int out_size)
{
    const float* x     = (const float*)d_in[0];
    const int*   ei    = (const int*)  d_in[1];
    const float* W1    = (const float*)d_in[2];
    const float* b1    = (const float*)d_in[3];
    const float* Wq    = (const float*)d_in[4];
    const float* bq    = (const float*)d_in[5];
    const float* Wk    = (const float*)d_in[6];
    const float* bk    = (const float*)d_in[7];
    const float* gamma = (const float*)d_in[8];
    const float* beta  = (const float*)d_in[9];
    const float* alpha = (const float*)d_in[10];
    const float* Wr    = (const float*)d_in[11];
    const float* br    = (const float*)d_in[12];
    const float* wgt   = (const float*)d_in[13];
    float* out = (float*)d_out;

    const int N = in_sizes[0] / FIN;
    const int E = in_sizes[1] / 2;
    const int* erow = ei;
    const int* ecol = ei + E;

    static bool attr_set = false;
    if (!attr_set) {
        cudaFuncSetAttribute(mma_gemm<0>, cudaFuncAttributeMaxDynamicSharedMemorySize, 2 * STAGE_BYTES);
        cudaFuncSetAttribute(mma_gemm<1>, cudaFuncAttributeMaxDynamicSharedMemorySize, 2 * STAGE_BYTES);
        cudaFuncSetAttribute(mma_gemm<2>, cudaFuncAttributeMaxDynamicSharedMemorySize, 2 * STAGE_BYTES);
        attr_set = true;
    }

    static float *pR = 0, *pRn = 0, *pKv = 0, *pStats = 0;
    static bf16 *pRh = 0, *pRl = 0, *pRTh = 0, *pRTl = 0, *pkTh = 0, *pkTl = 0,
                *pqkh = 0, *pqkl = 0, *pWTh = 0, *pWTl = 0, *pkvTh = 0, *pkvTl = 0;
    if (!pR) {
        cudaGetSymbolAddress((void**)&pR,    g_R);
        cudaGetSymbolAddress((void**)&pRn,   g_Rn);
        cudaGetSymbolAddress((void**)&pKv,   g_kv);
        cudaGetSymbolAddress((void**)&pStats,g_stats);
        cudaGetSymbolAddress((void**)&pRh,   g_Rh);
        cudaGetSymbolAddress((void**)&pRl,   g_Rl);
        cudaGetSymbolAddress((void**)&pRTh,  g_RTh);
        cudaGetSymbolAddress((void**)&pRTl,  g_RTl);
        cudaGetSymbolAddress((void**)&pkTh,  g_kTh);
        cudaGetSymbolAddress((void**)&pkTl,  g_kTl);
        cudaGetSymbolAddress((void**)&pqkh,  g_qkh);
        cudaGetSymbolAddress((void**)&pqkl,  g_qkl);
        cudaGetSymbolAddress((void**)&pWTh,  g_WqkTh);
        cudaGetSymbolAddress((void**)&pWTl,  g_WqkTl);
        cudaGetSymbolAddress((void**)&pkvTh, g_kvTh);
        cudaGetSymbolAddress((void**)&pkvTl, g_kvTl);
    }

    const int mtiles = (N + 127) / 128;
    const int tgrid = (N * 32 + 255) / 256;
    const int nb1 = (N + 1023) / 1024;

    // ---- CSR build (once per call) ----
    zero_i2     <<<(N + 255) / 256, 256>>>(N);
    cnt_deg     <<<(E + 255) / 256, 256>>>(ecol, E);
    invsqrt_k   <<<(N + 255) / 256, 256>>>(N);
    scan1       <<<nb1, 256>>>(N);
    scan2       <<<1, 128>>>(nb1);
    scan3       <<<(N + 255) / 256, 256>>>(N, E);
    edge_scatter<<<(E + 255) / 256, 256>>>(erow, ecol, E);

    build_wqkT<<<(2 * H * H + 255) / 256, 256>>>(Wq, Wk);

    // R = relu(x @ W1 + b1), with split-bf16 side output
    {
        dim3 g((H + 127) / 128, (N + 127) / 128);
        sgemm_relu<<<g, 256>>>(x, FIN, W1, H, b1, pR, H, N, FIN, pRh, pRl);
    }

    readout0<<<tgrid, 256>>>(Wr, br, wgt, out, N);

    for (int it = 0; it < 3; it++) {
        zero_k<<<(H * H + 255) / 256, 256>>>(pKv, H * H);
        zero_k<<<3, 256>>>(pStats, 2 + 2 * H);

        // [q|k] = R @ [Wq|Wk] + bias; q planes + kT planes + q2/k2/ksum stats
        mma_gemm<0><<<dim3(mtiles, 8, 1), 256, 2 * STAGE_BYTES>>>(
            pRh, pRl, 256, pWTh, pWTl, 256, N, 256, 256,
            bq, bk, nullptr, pqkh, pqkl, pkTh, pkTl);

        vsum_k<<<(N + 127) / 128, 256>>>(N);

        // v^T (= R^T) split planes (merged hi+lo)
        {
            dim3 g((N + 31) / 32, 8), b(32, 8);
            transpose2_bf16<<<g, b>>>(pRh, pRl, pRTh, pRTl, N, 256, N);
        }

        // kv = k^T @ v  (split-K over N, atomic fp32 merge)
        {
            int zchunks = (N + 511) / 512;
            mma_gemm<2><<<dim3(2, 4, zchunks), 256, 2 * STAGE_BYTES>>>(
                pkTh, pkTl, N, pRTh, pRTl, N, 256, N, 512,
                nullptr, nullptr, nullptr, nullptr, nullptr, nullptr, nullptr);
        }

        finalize_s<<<1, 1>>>();
        den_kernel<<<tgrid, 256>>>(N, (float)N);
        build_kvT<<<(H * H + 255) / 256, 256>>>();

        // Rn = (q @ kv * s + vsum) * invden
        mma_gemm<1><<<dim3(mtiles, 4, 1), 256, 2 * STAGE_BYTES>>>(
            pqkh, pqkl, 512, pkvTh, pkvTl, 256, N, 256, 256,
            nullptr, nullptr, pRn, nullptr, nullptr, nullptr, nullptr);

        // Rn += GCN(R)  via CSR gather, two 128-dim passes
        gcn_gather<<<(N + 7) / 8, 256>>>(N, 0);
        gcn_gather<<<(N + 7) / 8, 256>>>(N, 128);

        // R = LN(alpha*Rn + (1-alpha)*R); readout accumulate
        blend_ln<<<tgrid, 256>>>(alpha, gamma, beta, Wr, br, wgt, it + 1, out, N);
    }
}

// round 6
// speedup vs baseline: 2.4196x; 1.0151x over previous
#include <cuda_runtime.h>
#include <cuda_bf16.h>
#include <math.h>
#include <stdint.h>

#define H 256
#define FIN 58
#define N_MAX 100000
#define E_MAX 3200000

typedef __nv_bfloat16 bf16;

// ---------------- scratch (device globals; no allocation allowed) ------------
__device__ float g_R  [(size_t)N_MAX * H];
__device__ float g_Rn [(size_t)N_MAX * H];
__device__ bf16  g_Rh [(size_t)N_MAX * H];
__device__ bf16  g_Rl [(size_t)N_MAX * H];
__device__ bf16  g_RTh[(size_t)H * N_MAX];
__device__ bf16  g_RTl[(size_t)H * N_MAX];
__device__ bf16  g_kTh[(size_t)H * N_MAX];
__device__ bf16  g_kTl[(size_t)H * N_MAX];
__device__ bf16  g_qkh[(size_t)N_MAX * 2 * H];
__device__ bf16  g_qkl[(size_t)N_MAX * 2 * H];
__device__ bf16  g_WqkTh[2 * H * H];
__device__ bf16  g_WqkTl[2 * H * H];
__device__ bf16  g_kvTh[H * H];
__device__ bf16  g_kvTl[H * H];
__device__ float g_kv [H * H];
__device__ float g_dinv[N_MAX];
__device__ float g_invden[N_MAX];
__device__ float g_stats[2 + 2 * H];             // [q2, k2, ksum[256], vsum[256]]
__device__ float g_s[1];
// CSR structures
__device__ int   g_degi[N_MAX];
__device__ int   g_cur [N_MAX];
__device__ int   g_off [N_MAX + 1];
__device__ int   g_bsum[128];
__device__ int   g_esrc[E_MAX];
__device__ float g_ew  [E_MAX];

// ---------------- PTX helpers --------------------------------------------------
__device__ __forceinline__ uint32_t smem_u32(const void* p) {
    uint32_t a;
    asm("{ .reg .u64 t; cvta.to.shared.u64 t, %1; cvt.u32.u64 %0, t; }" : "=r"(a) : "l"(p));
    return a;
}
__device__ __forceinline__ void ldsm4(uint32_t* r, uint32_t addr) {
    asm volatile("ldmatrix.sync.aligned.m8n8.x4.shared.b16 {%0,%1,%2,%3}, [%4];"
                 : "=r"(r[0]), "=r"(r[1]), "=r"(r[2]), "=r"(r[3]) : "r"(addr));
}
__device__ __forceinline__ void mma16816(float* c, const uint32_t* a, uint32_t b0, uint32_t b1) {
    asm volatile("mma.sync.aligned.m16n8k16.row.col.f32.bf16.bf16.f32 "
                 "{%0,%1,%2,%3}, {%4,%5,%6,%7}, {%8,%9}, {%0,%1,%2,%3};"
                 : "+f"(c[0]), "+f"(c[1]), "+f"(c[2]), "+f"(c[3])
                 : "r"(a[0]), "r"(a[1]), "r"(a[2]), "r"(a[3]), "r"(b0), "r"(b1));
}
__device__ __forceinline__ void cpa16(uint32_t dst, const void* src, bool pred) {
    int sz = pred ? 16 : 0;
    asm volatile("cp.async.cg.shared.global [%0], [%1], 16, %2;"
                 :: "r"(dst), "l"(src), "r"(sz));
}
#define CP_COMMIT() asm volatile("cp.async.commit_group;" ::: "memory")
#define SW128(o) ((o) ^ (((o) >> 3) & 0x70))

// ---------------- tiny utility kernels ---------------------------------------
__global__ void zero_k(float* p, int n) {
    int i = blockIdx.x * blockDim.x + threadIdx.x;
    if (i < n) p[i] = 0.f;
}
__global__ void zero_i2(int n) {
    int i = blockIdx.x * blockDim.x + threadIdx.x;
    if (i < n) { g_degi[i] = 0; g_cur[i] = 0; }
}
__global__ void cnt_deg(const int* __restrict__ col, int E) {
    int i = blockIdx.x * blockDim.x + threadIdx.x;
    if (i < E) atomicAdd(&g_degi[col[i]], 1);
}
__global__ void invsqrt_k(int n) {
    int i = blockIdx.x * blockDim.x + threadIdx.x;
    if (i < n) {
        int d = g_degi[i];
        g_dinv[i] = (d > 0) ? rsqrtf((float)d) : 0.f;
    }
}
// ---- 2-level exclusive scan of g_degi -> g_off -------------------------------
__global__ __launch_bounds__(256) void scan1(int n) {
    __shared__ int s[256];
    int b = blockIdx.x, t = threadIdx.x;
    int base = b * 1024 + t * 4;
    int v0 = 0, v1 = 0, v2 = 0, v3 = 0;
    if (base + 0 < n) v0 = g_degi[base + 0];
    if (base + 1 < n) v1 = g_degi[base + 1];
    if (base + 2 < n) v2 = g_degi[base + 2];
    if (base + 3 < n) v3 = g_degi[base + 3];
    int tsum = v0 + v1 + v2 + v3;
    s[t] = tsum;
    __syncthreads();
    for (int o = 1; o < 256; o <<= 1) {
        int x = 0;
        if (t >= o) x = s[t - o];
        __syncthreads();
        s[t] += x;
        __syncthreads();
    }
    int ex = s[t] - tsum;
    if (base + 0 < n) g_off[base + 0] = ex;
    if (base + 1 < n) g_off[base + 1] = ex + v0;
    if (base + 2 < n) g_off[base + 2] = ex + v0 + v1;
    if (base + 3 < n) g_off[base + 3] = ex + v0 + v1 + v2;
    if (t == 255) g_bsum[b] = s[255];
}
__global__ void scan2(int nb) {
    __shared__ int s[128];
    int t = threadIdx.x;
    int v = (t < nb) ? g_bsum[t] : 0;
    s[t] = v;
    __syncthreads();
    for (int o = 1; o < 128; o <<= 1) {
        int x = 0;
        if (t >= o) x = s[t - o];
        __syncthreads();
        s[t] += x;
        __syncthreads();
    }
    g_bsum[t] = s[t] - v;
}
__global__ void scan3(int n, int E) {
    int i = blockIdx.x * blockDim.x + threadIdx.x;
    if (i < n) g_off[i] += g_bsum[i >> 10];
    if (i == 0) g_off[n] = E;
}
__global__ void edge_scatter(const int* __restrict__ erow, const int* __restrict__ ecol, int E) {
    int e = blockIdx.x * blockDim.x + threadIdx.x;
    if (e >= E) return;
    int c = ecol[e], r = erow[e];
    int pos = g_off[c] + atomicAdd(&g_cur[c], 1);
    g_esrc[pos] = r;
    g_ew[pos] = g_dinv[r] * g_dinv[c];
}

__device__ __forceinline__ void split_store(float v, bf16* ph, bf16* pl, size_t idx) {
    bf16 h = __float2bfloat16(v);
    ph[idx] = h;
    pl[idx] = __float2bfloat16(v - __bfloat162float(h));
}
__global__ void build_wqkT(const float* __restrict__ Wq, const float* __restrict__ Wk) {
    int idx = blockIdx.x * blockDim.x + threadIdx.x;
    if (idx >= 2 * H * H) return;
    int n = idx >> 8, k = idx & 255;
    float w = (n < H) ? Wq[k * H + n] : Wk[k * H + (n - H)];
    split_store(w, g_WqkTh, g_WqkTl, idx);
}
__global__ void build_kvT() {
    int idx = blockIdx.x * blockDim.x + threadIdx.x;
    if (idx >= H * H) return;
    int d = idx >> 8, m = idx & 255;
    split_store(g_kv[m * H + d], g_kvTh, g_kvTl, idx);
}
// merged hi+lo tiled transpose (used once per call, for iteration 0's R^T)
__global__ void transpose2_bf16(const bf16* __restrict__ ih, const bf16* __restrict__ il,
                                bf16* __restrict__ oh, bf16* __restrict__ ol,
                                int rows, int istride, int ostride) {
    __shared__ bf16 th[32][33], tl[32][33];
    int r0 = blockIdx.x * 32, c0 = blockIdx.y * 32;
    for (int i = threadIdx.y; i < 32; i += 8) {
        int r = r0 + i, c = c0 + threadIdx.x;
        bf16 zh = __float2bfloat16(0.f);
        th[i][threadIdx.x] = (r < rows) ? ih[(size_t)r * istride + c] : zh;
        tl[i][threadIdx.x] = (r < rows) ? il[(size_t)r * istride + c] : zh;
    }
    __syncthreads();
    for (int i = threadIdx.y; i < 32; i += 8) {
        int oc = r0 + threadIdx.x, orow = c0 + i;
        if (oc < rows) {
            oh[(size_t)orow * ostride + oc] = th[threadIdx.x][i];
            ol[(size_t)orow * ostride + oc] = tl[threadIdx.x][i];
        }
    }
}

// ---------------- fp32 SGEMM for x@W1 (K=58) with relu + split epilogue -------
__global__ __launch_bounds__(256) void sgemm_relu(
    const float* __restrict__ A, int lda,
    const float* __restrict__ B, int ldb,
    const float* __restrict__ bias,
    float* __restrict__ C, int ldc,
    int M, int K,
    bf16* __restrict__ Ch, bf16* __restrict__ Cl)
{
    __shared__ float As[8][128];
    __shared__ float Bs[8][128];
    const int tid = threadIdx.x;
    const int row0 = blockIdx.y * 128, col0 = blockIdx.x * 128;
    const int tr = tid >> 4, tc = tid & 15;
    const int ar = tid >> 1, as_ = (tid & 1) * 4;
    const int bkr = tid >> 5, bc = (tid & 31) * 4;

    float acc[8][8] = {};
    const int ksteps = (K + 7) / 8;
    for (int kt = 0; kt < ksteps; kt++) {
        int k0 = kt * 8;
        {
            int r = row0 + ar;
            #pragma unroll
            for (int j = 0; j < 4; j++) {
                int k = k0 + as_ + j;
                As[as_ + j][ar] = (r < M && k < K) ? A[(size_t)r * lda + k] : 0.f;
            }
        }
        {
            int k = k0 + bkr;
            float4 v = make_float4(0.f, 0.f, 0.f, 0.f);
            if (k < K) v = *(const float4*)&B[(size_t)k * ldb + col0 + bc];
            *(float4*)&Bs[bkr][bc] = v;
        }
        __syncthreads();
        #pragma unroll
        for (int kk = 0; kk < 8; kk++) {
            float a[8], b[8];
            *(float4*)&a[0] = *(const float4*)&As[kk][tr * 8];
            *(float4*)&a[4] = *(const float4*)&As[kk][tr * 8 + 4];
            *(float4*)&b[0] = *(const float4*)&Bs[kk][tc * 8];
            *(float4*)&b[4] = *(const float4*)&Bs[kk][tc * 8 + 4];
            #pragma unroll
            for (int i = 0; i < 8; i++)
                #pragma unroll
                for (int j = 0; j < 8; j++)
                    acc[i][j] += a[i] * b[j];
        }
        __syncthreads();
    }

    float bb[8];
    #pragma unroll
    for (int j = 0; j < 8; j++) bb[j] = bias[col0 + tc * 8 + j];
    #pragma unroll
    for (int i = 0; i < 8; i++) {
        int r = row0 + tr * 8 + i;
        if (r >= M) continue;
        #pragma unroll
        for (int j = 0; j < 8; j++) {
            int c = col0 + tc * 8 + j;
            float val = fmaxf(acc[i][j] + bb[j], 0.f);
            size_t idx = (size_t)r * ldc + c;
            C[idx] = val;
            split_store(val, Ch, Cl, idx);
        }
    }
}

// ---------------- mma.sync split-bf16 GEMM, 2-stage cp.async pipeline ---------
// Grid: x = N-block (fast-varying -> CTAs sharing an A tile run concurrently,
// so A re-reads hit L2), y = M-tile, z = K-chunk.
#define STAGE_BYTES 49152
template <int EPI>
__global__ __launch_bounds__(256, 2) void mma_gemm(
    const bf16* __restrict__ Ah_, const bf16* __restrict__ Al_, int lda,
    const bf16* __restrict__ Bh_, const bf16* __restrict__ Bl_, int ldb,
    int Mrows, int Ktot, int kchunk,
    const float* __restrict__ e0, const float* __restrict__ e1,
    float* __restrict__ outf, bf16* __restrict__ oh, bf16* __restrict__ ol,
    bf16* __restrict__ okTh, bf16* __restrict__ okTl)
{
    extern __shared__ char smem[];
    const int tid = threadIdx.x, wid = tid >> 5, lane = tid & 31;
    const int wm = (wid & 3) * 32;
    const int wn = (wid >> 2) * 32;
    const int row0 = blockIdx.y * 128;
    const int ncol0 = blockIdx.x * 64;
    const int k0 = blockIdx.z * kchunk;
    int kend = k0 + kchunk; if (kend > Ktot) kend = Ktot;
    const uint32_t sbase = smem_u32(smem);

    auto fill = [&](int stage, int ks) {
        uint32_t sa = sbase + stage * STAGE_BYTES;
        #pragma unroll
        for (int it = 0; it < 4; it++) {
            int ch = tid + it * 256;
            int r = ch >> 3, c8 = ch & 7;
            int g = row0 + r;
            int kb = ks + c8 * 8;
            uint32_t off = SW128((uint32_t)(r * 128 + c8 * 16));
            bool p = (g < Mrows) && (kb + 8 <= kend);
            const bf16* ph = p ? &Ah_[(size_t)g * lda + kb] : Ah_;
            const bf16* pl = p ? &Al_[(size_t)g * lda + kb] : Al_;
            cpa16(sa + off, ph, p);
            cpa16(sa + 16384 + off, pl, p);
        }
        #pragma unroll
        for (int it = 0; it < 2; it++) {
            int ch = tid + it * 256;
            int r = ch >> 3, c8 = ch & 7;
            int gn = ncol0 + r;
            int kb = ks + c8 * 8;
            uint32_t off = SW128((uint32_t)(r * 128 + c8 * 16));
            bool p = (kb + 8 <= kend);
            const bf16* ph = p ? &Bh_[(size_t)gn * ldb + kb] : Bh_;
            const bf16* pl = p ? &Bl_[(size_t)gn * ldb + kb] : Bl_;
            cpa16(sa + 32768 + off, ph, p);
            cpa16(sa + 40960 + off, pl, p);
        }
    };

    float acc[2][4][4] = {};
    int stage = 0;
    fill(0, k0);
    CP_COMMIT();

    for (int ks = k0; ks < kend; ks += 64) {
        int nxt = ks + 64;
        if (nxt < kend) {
            fill(stage ^ 1, nxt);
            CP_COMMIT();
            asm volatile("cp.async.wait_group 1;" ::: "memory");
        } else {
            asm volatile("cp.async.wait_group 0;" ::: "memory");
        }
        __syncthreads();

        uint32_t base = sbase + stage * STAGE_BYTES;
        #pragma unroll
        for (int kc = 0; kc < 4; kc++) {
            uint32_t ah[2][4], al[2][4], bh[2][4], bl[2][4];
            #pragma unroll
            for (int mt = 0; mt < 2; mt++) {
                uint32_t off = SW128((uint32_t)((wm + mt * 16 + (lane & 15)) * 128 +
                                                (kc * 16 + (lane >> 4) * 8) * 2));
                ldsm4(ah[mt], base + off);
                ldsm4(al[mt], base + 16384 + off);
            }
            #pragma unroll
            for (int ntp = 0; ntp < 2; ntp++) {
                uint32_t off = SW128((uint32_t)((wn + ntp * 16 + ((lane >> 4) & 1) * 8 + (lane & 7)) * 128 +
                                                (kc * 16 + ((lane >> 3) & 1) * 8) * 2));
                ldsm4(bh[ntp], base + 32768 + off);
                ldsm4(bl[ntp], base + 40960 + off);
            }
            #pragma unroll
            for (int mt = 0; mt < 2; mt++)
                #pragma unroll
                for (int nt = 0; nt < 4; nt++) {
                    uint32_t b0h = bh[nt >> 1][(nt & 1) * 2], b1h = bh[nt >> 1][(nt & 1) * 2 + 1];
                    uint32_t b0l = bl[nt >> 1][(nt & 1) * 2], b1l = bl[nt >> 1][(nt & 1) * 2 + 1];
                    mma16816(acc[mt][nt], ah[mt], b0h, b1h);
                    mma16816(acc[mt][nt], ah[mt], b0l, b1l);
                    mma16816(acc[mt][nt], al[mt], b0h, b1h);
                }
        }
        __syncthreads();
        stage ^= 1;
    }

    // ---- epilogues -----------------------------------------------------------
    if (EPI == 1) {
        float s_val = g_s[0];
        #pragma unroll
        for (int mt = 0; mt < 2; mt++)
            #pragma unroll
            for (int rg = 0; rg < 4; rg++) {
                int r = row0 + wm + mt * 16 + (lane >> 2) + ((rg >> 1) & 1) * 8;
                if (r >= Mrows) continue;
                #pragma unroll
                for (int nt = 0; nt < 4; nt++) {
                    int c = ncol0 + wn + nt * 8 + (lane & 3) * 2 + (rg & 1);
                    float v = (acc[mt][nt][rg] * s_val + g_stats[2 + H + c]) * g_invden[r];
                    outf[(size_t)r * H + c] = v;
                }
            }
    } else if (EPI == 2) {
        #pragma unroll
        for (int mt = 0; mt < 2; mt++)
            #pragma unroll
            for (int rg = 0; rg < 4; rg++) {
                int r = row0 + wm + mt * 16 + (lane >> 2) + ((rg >> 1) & 1) * 8;
                if (r >= Mrows) continue;
                #pragma unroll
                for (int nt = 0; nt < 4; nt++) {
                    int c = ncol0 + wn + nt * 8 + (lane & 3) * 2 + (rg & 1);
                    atomicAdd(&g_kv[(size_t)r * H + c], acc[mt][nt][rg]);
                }
            }
    } else {
        // EPI 0 — qk projection
        const bool is_k = (ncol0 >= 256);
        float* red_sm = (float*)(smem + 35328);
        float sq_part = 0.f;

        if (!is_k) {
            #pragma unroll
            for (int mt = 0; mt < 2; mt++)
                #pragma unroll
                for (int rg = 0; rg < 4; rg++) {
                    int r = row0 + wm + mt * 16 + (lane >> 2) + ((rg >> 1) & 1) * 8;
                    #pragma unroll
                    for (int nt = 0; nt < 4; nt++) {
                        int c = ncol0 + wn + nt * 8 + (lane & 3) * 2 + (rg & 1);
                        float v = 0.f;
                        if (r < Mrows) {
                            v = acc[mt][nt][rg] + e0[c];
                            split_store(v, oh, ol, (size_t)r * 512 + c);
                        }
                        sq_part += v * v;
                    }
                }
        } else {
            bf16* sTh = (bf16*)smem;                 // [64][136]
            bf16* sTl = (bf16*)(smem + 17408);
            float* ksum_sm = (float*)(smem + 34816); // [64]
            if (tid < 64) ksum_sm[tid] = 0.f;
            float colp[4][2];
            #pragma unroll
            for (int nt = 0; nt < 4; nt++) { colp[nt][0] = 0.f; colp[nt][1] = 0.f; }

            #pragma unroll
            for (int mt = 0; mt < 2; mt++)
                #pragma unroll
                for (int rg = 0; rg < 4; rg++) {
                    int rl = wm + mt * 16 + (lane >> 2) + ((rg >> 1) & 1) * 8;
                    int r = row0 + rl;
                    #pragma unroll
                    for (int nt = 0; nt < 4; nt++) {
                        int cl = wn + nt * 8 + (lane & 3) * 2 + (rg & 1);
                        float v = 0.f;
                        if (r < Mrows) v = acc[mt][nt][rg] + e1[ncol0 - 256 + cl];
                        sq_part += v * v;
                        colp[nt][rg & 1] += v;
                        bf16 h = __float2bfloat16(v);
                        sTh[cl * 136 + rl] = h;
                        sTl[cl * 136 + rl] = __float2bfloat16(v - __bfloat162float(h));
                    }
                }
            #pragma unroll
            for (int nt = 0; nt < 4; nt++)
                #pragma unroll
                for (int par = 0; par < 2; par++) {
                    float v = colp[nt][par];
                    v += __shfl_xor_sync(0xffffffffu, v, 4);
                    v += __shfl_xor_sync(0xffffffffu, v, 8);
                    v += __shfl_xor_sync(0xffffffffu, v, 16);
                    colp[nt][par] = v;
                }
            __syncthreads();
            if ((lane >> 2) == 0) {
                #pragma unroll
                for (int nt = 0; nt < 4; nt++)
                    #pragma unroll
                    for (int par = 0; par < 2; par++) {
                        int cl = wn + nt * 8 + (lane & 3) * 2 + par;
                        atomicAdd(&ksum_sm[cl], colp[nt][par]);
                    }
            }
            __syncthreads();
            if (tid < 64)
                atomicAdd(&g_stats[2 + (ncol0 - 256) + tid], ksum_sm[tid]);
            {
                int rowc = tid >> 2, quarter = tid & 3;
                int gk = ncol0 - 256 + rowc;
                size_t gb = (size_t)gk * (size_t)Mrows + row0;
                if (row0 + 128 <= Mrows) {
                    #pragma unroll
                    for (int j = 0; j < 4; j++) {
                        int rr = quarter * 32 + j * 8;
                        int4 vh = *(int4*)&sTh[rowc * 136 + rr];
                        int4 vl = *(int4*)&sTl[rowc * 136 + rr];
                        *(int4*)&okTh[gb + rr] = vh;
                        *(int4*)&okTl[gb + rr] = vl;
                    }
                } else {
                    for (int rr = quarter * 32; rr < quarter * 32 + 32; rr++) {
                        if (row0 + rr < Mrows) {
                            okTh[gb + rr] = sTh[rowc * 136 + rr];
                            okTl[gb + rr] = sTl[rowc * 136 + rr];
                        }
                    }
                }
            }
        }
        #pragma unroll
        for (int o = 16; o > 0; o >>= 1) sq_part += __shfl_xor_sync(0xffffffffu, sq_part, o);
        if (lane == 0) red_sm[wid] = sq_part;
        __syncthreads();
        if (tid == 0) {
            float t = 0.f;
            #pragma unroll
            for (int w = 0; w < 8; w++) t += red_sm[w];
            atomicAdd(&g_stats[is_k ? 1 : 0], t);
        }
    }
}

// ---------------- vsum: colsum of R ------------------------------------------
__global__ __launch_bounds__(256) void vsum_k(int M) {
    int t = threadIdx.x;
    int r0 = blockIdx.x * 128;
    int rend = r0 + 128; if (rend > M) rend = M;
    float vs = 0.f;
    for (int r = r0; r < rend; r++) vs += g_R[(size_t)r * 256 + t];
    atomicAdd(&g_stats[2 + 256 + t], vs);
}

__global__ void finalize_s() {
    g_s[0] = rsqrtf(g_stats[0]) * rsqrtf(g_stats[1]);
}

__global__ void den_kernel(int M, float fN) {
    int gw = (blockIdx.x * blockDim.x + threadIdx.x) >> 5;
    int l = threadIdx.x & 31;
    if (gw >= M) return;
    size_t base = (size_t)gw * 512;
    float sum = 0.f;
    #pragma unroll
    for (int j = 0; j < 8; j++) {
        int idx = j * 32 + l;
        float qv = __bfloat162float(g_qkh[base + idx]) + __bfloat162float(g_qkl[base + idx]);
        sum += qv * g_stats[2 + idx];
    }
    #pragma unroll
    for (int o = 16; o > 0; o >>= 1) sum += __shfl_xor_sync(0xffffffffu, sum, o);
    if (l == 0) g_invden[gw] = 1.0f / (g_s[0] * sum + fN);
}

// ---------------- GCN gather: Rn[c] += sum_e w[e] * R[src[e]] -----------------
__global__ __launch_bounds__(256) void gcn_gather(int Nn, int dimoff) {
    int warp = (blockIdx.x * blockDim.x + threadIdx.x) >> 5;
    if (warp >= Nn) return;
    int l = threadIdx.x & 31;
    int beg = g_off[warp], end = g_off[warp + 1];
    if (beg == end) return;
    float4 a = make_float4(0.f, 0.f, 0.f, 0.f);
    const float* Rbase = &g_R[(size_t)dimoff + l * 4];
    int e = beg;
    for (; e + 4 <= end; e += 4) {
        int s0 = __ldg(&g_esrc[e]);
        int s1 = __ldg(&g_esrc[e + 1]);
        int s2 = __ldg(&g_esrc[e + 2]);
        int s3 = __ldg(&g_esrc[e + 3]);
        float w0 = __ldg(&g_ew[e]);
        float w1 = __ldg(&g_ew[e + 1]);
        float w2 = __ldg(&g_ew[e + 2]);
        float w3 = __ldg(&g_ew[e + 3]);
        float4 v0 = *(const float4*)&Rbase[(size_t)s0 * 256];
        float4 v1 = *(const float4*)&Rbase[(size_t)s1 * 256];
        float4 v2 = *(const float4*)&Rbase[(size_t)s2 * 256];
        float4 v3 = *(const float4*)&Rbase[(size_t)s3 * 256];
        a.x += w0 * v0.x + w1 * v1.x + w2 * v2.x + w3 * v3.x;
        a.y += w0 * v0.y + w1 * v1.y + w2 * v2.y + w3 * v3.y;
        a.z += w0 * v0.z + w1 * v1.z + w2 * v2.z + w3 * v3.z;
        a.w += w0 * v0.w + w1 * v1.w + w2 * v2.w + w3 * v3.w;
    }
    for (; e < end; e++) {
        int s0 = __ldg(&g_esrc[e]);
        float w0 = __ldg(&g_ew[e]);
        float4 v0 = *(const float4*)&Rbase[(size_t)s0 * 256];
        a.x += w0 * v0.x; a.y += w0 * v0.y; a.z += w0 * v0.z; a.w += w0 * v0.w;
    }
    float4* dst = (float4*)&g_Rn[(size_t)warp * 256 + dimoff];
    float4 r = dst[l];
    r.x += a.x; r.y += a.y; r.z += a.z; r.w += a.w;
    dst[l] = r;
}

// ---------------- blend + LayerNorm + RT planes + readout ---------------------
// Block = 32 nodes x 256 dims. Writes R (fp32), Rh/Rl (row-major), and
// (if writeRT) RTh/RTl (dim-major) via smem staging.
__global__ __launch_bounds__(256) void blend_ln(
    const float* __restrict__ alpha_p,
    const float* __restrict__ gamma, const float* __restrict__ beta,
    const float* __restrict__ Wr, const float* __restrict__ br,
    const float* __restrict__ wgt, int sidx,
    float* __restrict__ out, int M, int writeRT)
{
    __shared__ bf16 sh[32][260];
    __shared__ bf16 sl[32][260];
    const int n0 = blockIdx.x * 32;
    const int wid = threadIdx.x >> 5, l = threadIdx.x & 31;
    const float al = alpha_p[0];
    const float* wr = Wr + sidx * 256;

    #pragma unroll
    for (int i = 0; i < 4; i++) {
        int nl = wid * 4 + i;
        int node = n0 + nl;
        if (node < M) {
            size_t base = (size_t)node * 256;
            float h[8]; float sum = 0.f, sq = 0.f;
            #pragma unroll
            for (int j = 0; j < 8; j++) {
                int idx = j * 32 + l;
                float v = al * g_Rn[base + idx] + (1.f - al) * g_R[base + idx];
                h[j] = v; sum += v; sq += v * v;
            }
            #pragma unroll
            for (int o = 16; o > 0; o >>= 1) {
                sum += __shfl_xor_sync(0xffffffffu, sum, o);
                sq  += __shfl_xor_sync(0xffffffffu, sq, o);
            }
            float mu  = sum * (1.f / 256.f);
            float var = sq * (1.f / 256.f) - mu * mu;
            float rstd = rsqrtf(var + 1e-5f);
            float dot = 0.f;
            #pragma unroll
            for (int j = 0; j < 8; j++) {
                int idx = j * 32 + l;
                float y = (h[j] - mu) * rstd * gamma[idx] + beta[idx];
                g_R[base + idx] = y;
                bf16 yh = __float2bfloat16(y);
                bf16 yl = __float2bfloat16(y - __bfloat162float(yh));
                g_Rh[base + idx] = yh;
                g_Rl[base + idx] = yl;
                sh[nl][idx] = yh;
                sl[nl][idx] = yl;
                dot += y * wr[idx];
            }
            #pragma unroll
            for (int o = 16; o > 0; o >>= 1) dot += __shfl_xor_sync(0xffffffffu, dot, o);
            if (l == 0) out[node] += wgt[sidx] * (dot + br[sidx]);
        }
    }

    if (writeRT) {
        __syncthreads();
        int d = threadIdx.x;                       // one dim per thread
        size_t Nn = (size_t)M;
        if (n0 + 32 <= M && ((Nn * 2) & 15) == 0) {
            uint32_t ph[16], pl[16];
            #pragma unroll
            for (int p = 0; p < 16; p++) {
                uint32_t h0 = __bfloat16_as_ushort(sh[p * 2][d]);
                uint32_t h1 = __bfloat16_as_ushort(sh[p * 2 + 1][d]);
                uint32_t l0 = __bfloat16_as_ushort(sl[p * 2][d]);
                uint32_t l1 = __bfloat16_as_ushort(sl[p * 2 + 1][d]);
                ph[p] = h0 | (h1 << 16);
                pl[p] = l0 | (l1 << 16);
            }
            size_t gb = (size_t)d * Nn + n0;
            #pragma unroll
            for (int q = 0; q < 4; q++) {
                *(int4*)&g_RTh[gb + q * 8] = *(int4*)&ph[q * 4];
                *(int4*)&g_RTl[gb + q * 8] = *(int4*)&pl[q * 4];
            }
        } else {
            for (int nl = 0; nl < 32; nl++) {
                if (n0 + nl < M) {
                    g_RTh[(size_t)d * Nn + n0 + nl] = sh[nl][d];
                    g_RTl[(size_t)d * Nn + n0 + nl] = sl[nl][d];
                }
            }
        }
    }
}

__global__ void readout0(const float* __restrict__ Wr, const float* __restrict__ br,
                         const float* __restrict__ wgt, float* __restrict__ out, int M)
{
    int gw = (blockIdx.x * blockDim.x + threadIdx.x) >> 5;
    int l = threadIdx.x & 31;
    if (gw >= M) return;
    float dot = 0.f;
    #pragma unroll
    for (int j = 0; j < 8; j++) {
        int idx = j * 32 + l;
        dot += g_R[(size_t)gw * 256 + idx] * Wr[idx];
    }
    #pragma unroll
    for (int o = 16; o > 0; o >>= 1) dot += __shfl_xor_sync(0xffffffffu, dot, o);
    if (l == 0) out[gw] = wgt[0] * (dot + br[0]);
}

// ---------------- host orchestration ------------------------------------------
extern "C" void kernel_launch(void* const* d_in, const int* in_sizes, int n_in,
                              void* d_out, int out_size)
{
    const float* x     = (const float*)d_in[0];
    const int*   ei    = (const int*)  d_in[1];
    const float* W1    = (const float*)d_in[2];
    const float* b1    = (const float*)d_in[3];
    const float* Wq    = (const float*)d_in[4];
    const float* bq    = (const float*)d_in[5];
    const float* Wk    = (const float*)d_in[6];
    const float* bk    = (const float*)d_in[7];
    const float* gamma = (const float*)d_in[8];
    const float* beta  = (const float*)d_in[9];
    const float* alpha = (const float*)d_in[10];
    const float* Wr    = (const float*)d_in[11];
    const float* br    = (const float*)d_in[12];
    const float* wgt   = (const float*)d_in[13];
    float* out = (float*)d_out;

    const int N = in_sizes[0] / FIN;
    const int E = in_sizes[1] / 2;
    const int* erow = ei;
    const int* ecol = ei + E;

    static bool attr_set = false;
    if (!attr_set) {
        cudaFuncSetAttribute(mma_gemm<0>, cudaFuncAttributeMaxDynamicSharedMemorySize, 2 * STAGE_BYTES);
        cudaFuncSetAttribute(mma_gemm<1>, cudaFuncAttributeMaxDynamicSharedMemorySize, 2 * STAGE_BYTES);
        cudaFuncSetAttribute(mma_gemm<2>, cudaFuncAttributeMaxDynamicSharedMemorySize, 2 * STAGE_BYTES);
        attr_set = true;
    }

    static float *pR = 0, *pRn = 0, *pKv = 0, *pStats = 0;
    static bf16 *pRh = 0, *pRl = 0, *pRTh = 0, *pRTl = 0, *pkTh = 0, *pkTl = 0,
                *pqkh = 0, *pqkl = 0, *pWTh = 0, *pWTl = 0, *pkvTh = 0, *pkvTl = 0;
    if (!pR) {
        cudaGetSymbolAddress((void**)&pR,    g_R);
        cudaGetSymbolAddress((void**)&pRn,   g_Rn);
        cudaGetSymbolAddress((void**)&pKv,   g_kv);
        cudaGetSymbolAddress((void**)&pStats,g_stats);
        cudaGetSymbolAddress((void**)&pRh,   g_Rh);
        cudaGetSymbolAddress((void**)&pRl,   g_Rl);
        cudaGetSymbolAddress((void**)&pRTh,  g_RTh);
        cudaGetSymbolAddress((void**)&pRTl,  g_RTl);
        cudaGetSymbolAddress((void**)&pkTh,  g_kTh);
        cudaGetSymbolAddress((void**)&pkTl,  g_kTl);
        cudaGetSymbolAddress((void**)&pqkh,  g_qkh);
        cudaGetSymbolAddress((void**)&pqkl,  g_qkl);
        cudaGetSymbolAddress((void**)&pWTh,  g_WqkTh);
        cudaGetSymbolAddress((void**)&pWTl,  g_WqkTl);
        cudaGetSymbolAddress((void**)&pkvTh, g_kvTh);
        cudaGetSymbolAddress((void**)&pkvTl, g_kvTl);
    }

    const int mtiles = (N + 127) / 128;
    const int tgrid = (N * 32 + 255) / 256;
    const int nb1 = (N + 1023) / 1024;

    // ---- CSR build (once per call) ----
    zero_i2     <<<(N + 255) / 256, 256>>>(N);
    cnt_deg     <<<(E + 255) / 256, 256>>>(ecol, E);
    invsqrt_k   <<<(N + 255) / 256, 256>>>(N);
    scan1       <<<nb1, 256>>>(N);
    scan2       <<<1, 128>>>(nb1);
    scan3       <<<(N + 255) / 256, 256>>>(N, E);
    edge_scatter<<<(E + 255) / 256, 256>>>(erow, ecol, E);

    build_wqkT<<<(2 * H * H + 255) / 256, 256>>>(Wq, Wk);

    // R = relu(x @ W1 + b1), with split-bf16 side output
    {
        dim3 g((H + 127) / 128, (N + 127) / 128);
        sgemm_relu<<<g, 256>>>(x, FIN, W1, H, b1, pR, H, N, FIN, pRh, pRl);
    }

    readout0<<<tgrid, 256>>>(Wr, br, wgt, out, N);

    // R^T planes for iteration 0 (later iterations: fused into blend_ln)
    {
        dim3 g((N + 31) / 32, 8), b(32, 8);
        transpose2_bf16<<<g, b>>>(pRh, pRl, pRTh, pRTl, N, 256, N);
    }

    for (int it = 0; it < 3; it++) {
        zero_k<<<(H * H + 255) / 256, 256>>>(pKv, H * H);
        zero_k<<<3, 256>>>(pStats, 2 + 2 * H);

        // [q|k] = R @ [Wq|Wk] + bias; q planes + kT planes + q2/k2/ksum stats
        mma_gemm<0><<<dim3(8, mtiles, 1), 256, 2 * STAGE_BYTES>>>(
            pRh, pRl, 256, pWTh, pWTl, 256, N, 256, 256,
            bq, bk, nullptr, pqkh, pqkl, pkTh, pkTl);

        vsum_k<<<(N + 127) / 128, 256>>>(N);

        // kv = k^T @ v  (split-K over N, atomic fp32 merge)
        {
            int zchunks = (N + 1023) / 1024;
            mma_gemm<2><<<dim3(4, 2, zchunks), 256, 2 * STAGE_BYTES>>>(
                pkTh, pkTl, N, pRTh, pRTl, N, 256, N, 1024,
                nullptr, nullptr, nullptr, nullptr, nullptr, nullptr, nullptr);
        }

        finalize_s<<<1, 1>>>();
        den_kernel<<<tgrid, 256>>>(N, (float)N);
        build_kvT<<<(H * H + 255) / 256, 256>>>();

        // Rn = (q @ kv * s + vsum) * invden
        mma_gemm<1><<<dim3(4, mtiles, 1), 256, 2 * STAGE_BYTES>>>(
            pqkh, pqkl, 512, pkvTh, pkvTl, 256, N, 256, 256,
            nullptr, nullptr, pRn, nullptr, nullptr, nullptr, nullptr);

        // Rn += GCN(R)  via CSR gather, two 128-dim passes
        gcn_gather<<<(N + 7) / 8, 256>>>(N, 0);
        gcn_gather<<<(N + 7) / 8, 256>>>(N, 128);

        // R = LN(alpha*Rn + (1-alpha)*R); RT planes for next iter; readout
        blend_ln<<<(N + 31) / 32, 256>>>(alpha, gamma, beta, Wr, br, wgt,
                                         it + 1, out, N, it < 2 ? 1 : 0);
    }
}

// round 7
// speedup vs baseline: 2.5615x; 1.0587x over previous
#include <cuda_runtime.h>
#include <cuda_bf16.h>
#include <math.h>
#include <stdint.h>

#define H 256
#define FIN 58
#define N_MAX 100000
#define E_MAX 3200000

typedef __nv_bfloat16 bf16;

// ---------------- scratch (device globals; no allocation allowed) ------------
__device__ float g_R  [(size_t)N_MAX * H];
__device__ float g_Rn [(size_t)N_MAX * H];      // attention output
__device__ float g_Gn [(size_t)N_MAX * H];      // gcn output (separate: breaks dep)
__device__ bf16  g_Rh [(size_t)N_MAX * H];
__device__ bf16  g_Rl [(size_t)N_MAX * H];
__device__ bf16  g_RTh[(size_t)H * N_MAX];
__device__ bf16  g_RTl[(size_t)H * N_MAX];
__device__ bf16  g_kTh[(size_t)H * N_MAX];
__device__ bf16  g_kTl[(size_t)H * N_MAX];
__device__ bf16  g_qkh[(size_t)N_MAX * 2 * H];
__device__ bf16  g_qkl[(size_t)N_MAX * 2 * H];
__device__ bf16  g_WqkTh[2 * H * H];
__device__ bf16  g_WqkTl[2 * H * H];
__device__ bf16  g_kvTh[H * H];
__device__ bf16  g_kvTl[H * H];
__device__ float g_kv [H * H];
__device__ float g_dinv[N_MAX];
__device__ float g_invden[N_MAX];
__device__ float g_stats[2 + 2 * H];             // [q2, k2, ksum[256], vsum[256]]
__device__ float g_s[1];
// CSR structures
__device__ int   g_degi[N_MAX];
__device__ int   g_cur [N_MAX];
__device__ int   g_off [N_MAX + 1];
__device__ int   g_bsum[128];
__device__ int   g_esrc[E_MAX];
__device__ float g_ew  [E_MAX];

// ---------------- PTX helpers --------------------------------------------------
__device__ __forceinline__ uint32_t smem_u32(const void* p) {
    uint32_t a;
    asm("{ .reg .u64 t; cvta.to.shared.u64 t, %1; cvt.u32.u64 %0, t; }" : "=r"(a) : "l"(p));
    return a;
}
__device__ __forceinline__ void ldsm4(uint32_t* r, uint32_t addr) {
    asm volatile("ldmatrix.sync.aligned.m8n8.x4.shared.b16 {%0,%1,%2,%3}, [%4];"
                 : "=r"(r[0]), "=r"(r[1]), "=r"(r[2]), "=r"(r[3]) : "r"(addr));
}
__device__ __forceinline__ void mma16816(float* c, const uint32_t* a, uint32_t b0, uint32_t b1) {
    asm volatile("mma.sync.aligned.m16n8k16.row.col.f32.bf16.bf16.f32 "
                 "{%0,%1,%2,%3}, {%4,%5,%6,%7}, {%8,%9}, {%0,%1,%2,%3};"
                 : "+f"(c[0]), "+f"(c[1]), "+f"(c[2]), "+f"(c[3])
                 : "r"(a[0]), "r"(a[1]), "r"(a[2]), "r"(a[3]), "r"(b0), "r"(b1));
}
__device__ __forceinline__ void cpa16(uint32_t dst, const void* src, bool pred) {
    int sz = pred ? 16 : 0;
    asm volatile("cp.async.cg.shared.global [%0], [%1], 16, %2;"
                 :: "r"(dst), "l"(src), "r"(sz));
}
#define CP_COMMIT() asm volatile("cp.async.commit_group;" ::: "memory")
#define SW128(o) ((o) ^ (((o) >> 3) & 0x70))

// ---------------- tiny utility kernels ---------------------------------------
__global__ void zero_k(float* p, int n) {
    int i = blockIdx.x * blockDim.x + threadIdx.x;
    if (i < n) p[i] = 0.f;
}
__global__ void zero_i2(int n) {
    int i = blockIdx.x * blockDim.x + threadIdx.x;
    if (i < n) { g_degi[i] = 0; g_cur[i] = 0; }
}
__global__ void cnt_deg(const int* __restrict__ col, int E) {
    int i = blockIdx.x * blockDim.x + threadIdx.x;
    if (i < E) atomicAdd(&g_degi[col[i]], 1);
}
__global__ void invsqrt_k(int n) {
    int i = blockIdx.x * blockDim.x + threadIdx.x;
    if (i < n) {
        int d = g_degi[i];
        g_dinv[i] = (d > 0) ? rsqrtf((float)d) : 0.f;
    }
}
// ---- 2-level exclusive scan of g_degi -> g_off -------------------------------
__global__ __launch_bounds__(256) void scan1(int n) {
    __shared__ int s[256];
    int b = blockIdx.x, t = threadIdx.x;
    int base = b * 1024 + t * 4;
    int v0 = 0, v1 = 0, v2 = 0, v3 = 0;
    if (base + 0 < n) v0 = g_degi[base + 0];
    if (base + 1 < n) v1 = g_degi[base + 1];
    if (base + 2 < n) v2 = g_degi[base + 2];
    if (base + 3 < n) v3 = g_degi[base + 3];
    int tsum = v0 + v1 + v2 + v3;
    s[t] = tsum;
    __syncthreads();
    for (int o = 1; o < 256; o <<= 1) {
        int x = 0;
        if (t >= o) x = s[t - o];
        __syncthreads();
        s[t] += x;
        __syncthreads();
    }
    int ex = s[t] - tsum;
    if (base + 0 < n) g_off[base + 0] = ex;
    if (base + 1 < n) g_off[base + 1] = ex + v0;
    if (base + 2 < n) g_off[base + 2] = ex + v0 + v1;
    if (base + 3 < n) g_off[base + 3] = ex + v0 + v1 + v2;
    if (t == 255) g_bsum[b] = s[255];
}
__global__ void scan2(int nb) {
    __shared__ int s[128];
    int t = threadIdx.x;
    int v = (t < nb) ? g_bsum[t] : 0;
    s[t] = v;
    __syncthreads();
    for (int o = 1; o < 128; o <<= 1) {
        int x = 0;
        if (t >= o) x = s[t - o];
        __syncthreads();
        s[t] += x;
        __syncthreads();
    }
    g_bsum[t] = s[t] - v;
}
__global__ void scan3(int n, int E) {
    int i = blockIdx.x * blockDim.x + threadIdx.x;
    if (i < n) g_off[i] += g_bsum[i >> 10];
    if (i == 0) g_off[n] = E;
}
__global__ void edge_scatter(const int* __restrict__ erow, const int* __restrict__ ecol, int E) {
    int e = blockIdx.x * blockDim.x + threadIdx.x;
    if (e >= E) return;
    int c = ecol[e], r = erow[e];
    int pos = g_off[c] + atomicAdd(&g_cur[c], 1);
    g_esrc[pos] = r;
    g_ew[pos] = g_dinv[r] * g_dinv[c];
}

__device__ __forceinline__ void split_store(float v, bf16* ph, bf16* pl, size_t idx) {
    bf16 h = __float2bfloat16(v);
    ph[idx] = h;
    pl[idx] = __float2bfloat16(v - __bfloat162float(h));
}
__global__ void build_wqkT(const float* __restrict__ Wq, const float* __restrict__ Wk) {
    int idx = blockIdx.x * blockDim.x + threadIdx.x;
    if (idx >= 2 * H * H) return;
    int n = idx >> 8, k = idx & 255;
    float w = (n < H) ? Wq[k * H + n] : Wk[k * H + (n - H)];
    split_store(w, g_WqkTh, g_WqkTl, idx);
}
__global__ void build_kvT() {
    int idx = blockIdx.x * blockDim.x + threadIdx.x;
    if (idx >= H * H) return;
    int d = idx >> 8, m = idx & 255;
    split_store(g_kv[m * H + d], g_kvTh, g_kvTl, idx);
}
// merged hi+lo tiled transpose (used once per call, for iteration 0's R^T)
__global__ void transpose2_bf16(const bf16* __restrict__ ih, const bf16* __restrict__ il,
                                bf16* __restrict__ oh, bf16* __restrict__ ol,
                                int rows, int istride, int ostride) {
    __shared__ bf16 th[32][33], tl[32][33];
    int r0 = blockIdx.x * 32, c0 = blockIdx.y * 32;
    for (int i = threadIdx.y; i < 32; i += 8) {
        int r = r0 + i, c = c0 + threadIdx.x;
        bf16 zh = __float2bfloat16(0.f);
        th[i][threadIdx.x] = (r < rows) ? ih[(size_t)r * istride + c] : zh;
        tl[i][threadIdx.x] = (r < rows) ? il[(size_t)r * istride + c] : zh;
    }
    __syncthreads();
    for (int i = threadIdx.y; i < 32; i += 8) {
        int oc = r0 + threadIdx.x, orow = c0 + i;
        if (oc < rows) {
            oh[(size_t)orow * ostride + oc] = th[threadIdx.x][i];
            ol[(size_t)orow * ostride + oc] = tl[threadIdx.x][i];
        }
    }
}

// ---------------- fp32 SGEMM for x@W1 (K=58) with relu + split epilogue -------
__global__ __launch_bounds__(256) void sgemm_relu(
    const float* __restrict__ A, int lda,
    const float* __restrict__ B, int ldb,
    const float* __restrict__ bias,
    float* __restrict__ C, int ldc,
    int M, int K,
    bf16* __restrict__ Ch, bf16* __restrict__ Cl)
{
    __shared__ float As[8][128];
    __shared__ float Bs[8][128];
    const int tid = threadIdx.x;
    const int row0 = blockIdx.y * 128, col0 = blockIdx.x * 128;
    const int tr = tid >> 4, tc = tid & 15;
    const int ar = tid >> 1, as_ = (tid & 1) * 4;
    const int bkr = tid >> 5, bc = (tid & 31) * 4;

    float acc[8][8] = {};
    const int ksteps = (K + 7) / 8;
    for (int kt = 0; kt < ksteps; kt++) {
        int k0 = kt * 8;
        {
            int r = row0 + ar;
            #pragma unroll
            for (int j = 0; j < 4; j++) {
                int k = k0 + as_ + j;
                As[as_ + j][ar] = (r < M && k < K) ? A[(size_t)r * lda + k] : 0.f;
            }
        }
        {
            int k = k0 + bkr;
            float4 v = make_float4(0.f, 0.f, 0.f, 0.f);
            if (k < K) v = *(const float4*)&B[(size_t)k * ldb + col0 + bc];
            *(float4*)&Bs[bkr][bc] = v;
        }
        __syncthreads();
        #pragma unroll
        for (int kk = 0; kk < 8; kk++) {
            float a[8], b[8];
            *(float4*)&a[0] = *(const float4*)&As[kk][tr * 8];
            *(float4*)&a[4] = *(const float4*)&As[kk][tr * 8 + 4];
            *(float4*)&b[0] = *(const float4*)&Bs[kk][tc * 8];
            *(float4*)&b[4] = *(const float4*)&Bs[kk][tc * 8 + 4];
            #pragma unroll
            for (int i = 0; i < 8; i++)
                #pragma unroll
                for (int j = 0; j < 8; j++)
                    acc[i][j] += a[i] * b[j];
        }
        __syncthreads();
    }

    float bb[8];
    #pragma unroll
    for (int j = 0; j < 8; j++) bb[j] = bias[col0 + tc * 8 + j];
    #pragma unroll
    for (int i = 0; i < 8; i++) {
        int r = row0 + tr * 8 + i;
        if (r >= M) continue;
        #pragma unroll
        for (int j = 0; j < 8; j++) {
            int c = col0 + tc * 8 + j;
            float val = fmaxf(acc[i][j] + bb[j], 0.f);
            size_t idx = (size_t)r * ldc + c;
            C[idx] = val;
            split_store(val, Ch, Cl, idx);
        }
    }
}

// ---------------- mma.sync split-bf16 GEMM, 2-stage cp.async pipeline ---------
#define STAGE_BYTES 49152
template <int EPI>
__global__ __launch_bounds__(256, 2) void mma_gemm(
    const bf16* __restrict__ Ah_, const bf16* __restrict__ Al_, int lda,
    const bf16* __restrict__ Bh_, const bf16* __restrict__ Bl_, int ldb,
    int Mrows, int Ktot, int kchunk,
    const float* __restrict__ e0, const float* __restrict__ e1,
    float* __restrict__ outf, bf16* __restrict__ oh, bf16* __restrict__ ol,
    bf16* __restrict__ okTh, bf16* __restrict__ okTl)
{
    extern __shared__ char smem[];
    const int tid = threadIdx.x, wid = tid >> 5, lane = tid & 31;
    const int wm = (wid & 3) * 32;
    const int wn = (wid >> 2) * 32;
    const int row0 = blockIdx.y * 128;
    const int ncol0 = blockIdx.x * 64;
    const int k0 = blockIdx.z * kchunk;
    int kend = k0 + kchunk; if (kend > Ktot) kend = Ktot;
    const uint32_t sbase = smem_u32(smem);

    auto fill = [&](int stage, int ks) {
        uint32_t sa = sbase + stage * STAGE_BYTES;
        #pragma unroll
        for (int it = 0; it < 4; it++) {
            int ch = tid + it * 256;
            int r = ch >> 3, c8 = ch & 7;
            int g = row0 + r;
            int kb = ks + c8 * 8;
            uint32_t off = SW128((uint32_t)(r * 128 + c8 * 16));
            bool p = (g < Mrows) && (kb + 8 <= kend);
            const bf16* ph = p ? &Ah_[(size_t)g * lda + kb] : Ah_;
            const bf16* pl = p ? &Al_[(size_t)g * lda + kb] : Al_;
            cpa16(sa + off, ph, p);
            cpa16(sa + 16384 + off, pl, p);
        }
        #pragma unroll
        for (int it = 0; it < 2; it++) {
            int ch = tid + it * 256;
            int r = ch >> 3, c8 = ch & 7;
            int gn = ncol0 + r;
            int kb = ks + c8 * 8;
            uint32_t off = SW128((uint32_t)(r * 128 + c8 * 16));
            bool p = (kb + 8 <= kend);
            const bf16* ph = p ? &Bh_[(size_t)gn * ldb + kb] : Bh_;
            const bf16* pl = p ? &Bl_[(size_t)gn * ldb + kb] : Bl_;
            cpa16(sa + 32768 + off, ph, p);
            cpa16(sa + 40960 + off, pl, p);
        }
    };

    float acc[2][4][4] = {};
    int stage = 0;
    fill(0, k0);
    CP_COMMIT();

    for (int ks = k0; ks < kend; ks += 64) {
        int nxt = ks + 64;
        if (nxt < kend) {
            fill(stage ^ 1, nxt);
            CP_COMMIT();
            asm volatile("cp.async.wait_group 1;" ::: "memory");
        } else {
            asm volatile("cp.async.wait_group 0;" ::: "memory");
        }
        __syncthreads();

        uint32_t base = sbase + stage * STAGE_BYTES;
        #pragma unroll
        for (int kc = 0; kc < 4; kc++) {
            uint32_t ah[2][4], al[2][4], bh[2][4], bl[2][4];
            #pragma unroll
            for (int mt = 0; mt < 2; mt++) {
                uint32_t off = SW128((uint32_t)((wm + mt * 16 + (lane & 15)) * 128 +
                                                (kc * 16 + (lane >> 4) * 8) * 2));
                ldsm4(ah[mt], base + off);
                ldsm4(al[mt], base + 16384 + off);
            }
            #pragma unroll
            for (int ntp = 0; ntp < 2; ntp++) {
                uint32_t off = SW128((uint32_t)((wn + ntp * 16 + ((lane >> 4) & 1) * 8 + (lane & 7)) * 128 +
                                                (kc * 16 + ((lane >> 3) & 1) * 8) * 2));
                ldsm4(bh[ntp], base + 32768 + off);
                ldsm4(bl[ntp], base + 40960 + off);
            }
            #pragma unroll
            for (int mt = 0; mt < 2; mt++)
                #pragma unroll
                for (int nt = 0; nt < 4; nt++) {
                    uint32_t b0h = bh[nt >> 1][(nt & 1) * 2], b1h = bh[nt >> 1][(nt & 1) * 2 + 1];
                    uint32_t b0l = bl[nt >> 1][(nt & 1) * 2], b1l = bl[nt >> 1][(nt & 1) * 2 + 1];
                    mma16816(acc[mt][nt], ah[mt], b0h, b1h);
                    mma16816(acc[mt][nt], ah[mt], b0l, b1l);
                    mma16816(acc[mt][nt], al[mt], b0h, b1h);
                }
        }
        __syncthreads();
        stage ^= 1;
    }

    // ---- epilogues -----------------------------------------------------------
    if (EPI == 1) {
        float s_val = g_s[0];
        #pragma unroll
        for (int mt = 0; mt < 2; mt++)
            #pragma unroll
            for (int rg = 0; rg < 4; rg++) {
                int r = row0 + wm + mt * 16 + (lane >> 2) + ((rg >> 1) & 1) * 8;
                if (r >= Mrows) continue;
                #pragma unroll
                for (int nt = 0; nt < 4; nt++) {
                    int c = ncol0 + wn + nt * 8 + (lane & 3) * 2 + (rg & 1);
                    float v = (acc[mt][nt][rg] * s_val + g_stats[2 + H + c]) * g_invden[r];
                    outf[(size_t)r * H + c] = v;
                }
            }
    } else if (EPI == 2) {
        #pragma unroll
        for (int mt = 0; mt < 2; mt++)
            #pragma unroll
            for (int rg = 0; rg < 4; rg++) {
                int r = row0 + wm + mt * 16 + (lane >> 2) + ((rg >> 1) & 1) * 8;
                if (r >= Mrows) continue;
                #pragma unroll
                for (int nt = 0; nt < 4; nt++) {
                    int c = ncol0 + wn + nt * 8 + (lane & 3) * 2 + (rg & 1);
                    atomicAdd(&g_kv[(size_t)r * H + c], acc[mt][nt][rg]);
                }
            }
    } else {
        // EPI 0 — qk projection
        const bool is_k = (ncol0 >= 256);
        float* red_sm = (float*)(smem + 35328);
        float sq_part = 0.f;

        if (!is_k) {
            #pragma unroll
            for (int mt = 0; mt < 2; mt++)
                #pragma unroll
                for (int rg = 0; rg < 4; rg++) {
                    int r = row0 + wm + mt * 16 + (lane >> 2) + ((rg >> 1) & 1) * 8;
                    #pragma unroll
                    for (int nt = 0; nt < 4; nt++) {
                        int c = ncol0 + wn + nt * 8 + (lane & 3) * 2 + (rg & 1);
                        float v = 0.f;
                        if (r < Mrows) {
                            v = acc[mt][nt][rg] + e0[c];
                            split_store(v, oh, ol, (size_t)r * 512 + c);
                        }
                        sq_part += v * v;
                    }
                }
        } else {
            bf16* sTh = (bf16*)smem;                 // [64][136]
            bf16* sTl = (bf16*)(smem + 17408);
            float* ksum_sm = (float*)(smem + 34816); // [64]
            if (tid < 64) ksum_sm[tid] = 0.f;
            float colp[4][2];
            #pragma unroll
            for (int nt = 0; nt < 4; nt++) { colp[nt][0] = 0.f; colp[nt][1] = 0.f; }

            #pragma unroll
            for (int mt = 0; mt < 2; mt++)
                #pragma unroll
                for (int rg = 0; rg < 4; rg++) {
                    int rl = wm + mt * 16 + (lane >> 2) + ((rg >> 1) & 1) * 8;
                    int r = row0 + rl;
                    #pragma unroll
                    for (int nt = 0; nt < 4; nt++) {
                        int cl = wn + nt * 8 + (lane & 3) * 2 + (rg & 1);
                        float v = 0.f;
                        if (r < Mrows) v = acc[mt][nt][rg] + e1[ncol0 - 256 + cl];
                        sq_part += v * v;
                        colp[nt][rg & 1] += v;
                        bf16 h = __float2bfloat16(v);
                        sTh[cl * 136 + rl] = h;
                        sTl[cl * 136 + rl] = __float2bfloat16(v - __bfloat162float(h));
                    }
                }
            #pragma unroll
            for (int nt = 0; nt < 4; nt++)
                #pragma unroll
                for (int par = 0; par < 2; par++) {
                    float v = colp[nt][par];
                    v += __shfl_xor_sync(0xffffffffu, v, 4);
                    v += __shfl_xor_sync(0xffffffffu, v, 8);
                    v += __shfl_xor_sync(0xffffffffu, v, 16);
                    colp[nt][par] = v;
                }
            __syncthreads();
            if ((lane >> 2) == 0) {
                #pragma unroll
                for (int nt = 0; nt < 4; nt++)
                    #pragma unroll
                    for (int par = 0; par < 2; par++) {
                        int cl = wn + nt * 8 + (lane & 3) * 2 + par;
                        atomicAdd(&ksum_sm[cl], colp[nt][par]);
                    }
            }
            __syncthreads();
            if (tid < 64)
                atomicAdd(&g_stats[2 + (ncol0 - 256) + tid], ksum_sm[tid]);
            {
                int rowc = tid >> 2, quarter = tid & 3;
                int gk = ncol0 - 256 + rowc;
                size_t gb = (size_t)gk * (size_t)Mrows + row0;
                if (row0 + 128 <= Mrows) {
                    #pragma unroll
                    for (int j = 0; j < 4; j++) {
                        int rr = quarter * 32 + j * 8;
                        int4 vh = *(int4*)&sTh[rowc * 136 + rr];
                        int4 vl = *(int4*)&sTl[rowc * 136 + rr];
                        *(int4*)&okTh[gb + rr] = vh;
                        *(int4*)&okTl[gb + rr] = vl;
                    }
                } else {
                    for (int rr = quarter * 32; rr < quarter * 32 + 32; rr++) {
                        if (row0 + rr < Mrows) {
                            okTh[gb + rr] = sTh[rowc * 136 + rr];
                            okTl[gb + rr] = sTl[rowc * 136 + rr];
                        }
                    }
                }
            }
        }
        #pragma unroll
        for (int o = 16; o > 0; o >>= 1) sq_part += __shfl_xor_sync(0xffffffffu, sq_part, o);
        if (lane == 0) red_sm[wid] = sq_part;
        __syncthreads();
        if (tid == 0) {
            float t = 0.f;
            #pragma unroll
            for (int w = 0; w < 8; w++) t += red_sm[w];
            atomicAdd(&g_stats[is_k ? 1 : 0], t);
        }
    }
}

// ---------------- vsum: colsum of R ------------------------------------------
__global__ __launch_bounds__(256) void vsum_k(int M) {
    int t = threadIdx.x;
    int r0 = blockIdx.x * 128;
    int rend = r0 + 128; if (rend > M) rend = M;
    float vs = 0.f;
    for (int r = r0; r < rend; r++) vs += g_R[(size_t)r * 256 + t];
    atomicAdd(&g_stats[2 + 256 + t], vs);
}

__global__ void finalize_s() {
    g_s[0] = rsqrtf(g_stats[0]) * rsqrtf(g_stats[1]);
}

__global__ void den_kernel(int M, float fN) {
    int gw = (blockIdx.x * blockDim.x + threadIdx.x) >> 5;
    int l = threadIdx.x & 31;
    if (gw >= M) return;
    size_t base = (size_t)gw * 512;
    float sum = 0.f;
    #pragma unroll
    for (int j = 0; j < 8; j++) {
        int idx = j * 32 + l;
        float qv = __bfloat162float(g_qkh[base + idx]) + __bfloat162float(g_qkl[base + idx]);
        sum += qv * g_stats[2 + idx];
    }
    #pragma unroll
    for (int o = 16; o > 0; o >>= 1) sum += __shfl_xor_sync(0xffffffffu, sum, o);
    if (l == 0) g_invden[gw] = 1.0f / (g_s[0] * sum + fN);
}

// ---------------- GCN gather (bf16, single 256-dim pass, writes Gn) -----------
// One warp per destination node; each lane covers 8 contiguous dims (16 B).
__global__ __launch_bounds__(256) void gcn_gather_bf16(int Nn) {
    int warp = (blockIdx.x * blockDim.x + threadIdx.x) >> 5;
    if (warp >= Nn) return;
    int l = threadIdx.x & 31;
    int beg = g_off[warp], end = g_off[warp + 1];
    float a[8] = {};
    const int4* Rb = (const int4*)g_Rh;       // 32 int4 per node row
    int e = beg;
    for (; e + 2 <= end; e += 2) {
        int s0 = __ldg(&g_esrc[e]);
        int s1 = __ldg(&g_esrc[e + 1]);
        float w0 = __ldg(&g_ew[e]);
        float w1 = __ldg(&g_ew[e + 1]);
        int4 p0 = __ldg(&Rb[(size_t)s0 * 32 + l]);
        int4 p1 = __ldg(&Rb[(size_t)s1 * 32 + l]);
        const uint32_t* u0 = (const uint32_t*)&p0;
        const uint32_t* u1 = (const uint32_t*)&p1;
        #pragma unroll
        for (int j = 0; j < 4; j++) {
            a[2 * j]     += w0 * __uint_as_float(u0[j] << 16)
                          + w1 * __uint_as_float(u1[j] << 16);
            a[2 * j + 1] += w0 * __uint_as_float(u0[j] & 0xffff0000u)
                          + w1 * __uint_as_float(u1[j] & 0xffff0000u);
        }
    }
    if (e < end) {
        int s0 = __ldg(&g_esrc[e]);
        float w0 = __ldg(&g_ew[e]);
        int4 p0 = __ldg(&Rb[(size_t)s0 * 32 + l]);
        const uint32_t* u0 = (const uint32_t*)&p0;
        #pragma unroll
        for (int j = 0; j < 4; j++) {
            a[2 * j]     += w0 * __uint_as_float(u0[j] << 16);
            a[2 * j + 1] += w0 * __uint_as_float(u0[j] & 0xffff0000u);
        }
    }
    float* dst = &g_Gn[(size_t)warp * 256 + l * 8];
    *(float4*)&dst[0] = *(float4*)&a[0];
    *(float4*)&dst[4] = *(float4*)&a[4];
}

// ---------------- blend + LayerNorm + RT planes + readout ---------------------
__global__ __launch_bounds__(256) void blend_ln(
    const float* __restrict__ alpha_p,
    const float* __restrict__ gamma, const float* __restrict__ beta,
    const float* __restrict__ Wr, const float* __restrict__ br,
    const float* __restrict__ wgt, int sidx,
    float* __restrict__ out, int M, int writeRT)
{
    __shared__ bf16 sh[32][260];
    __shared__ bf16 sl[32][260];
    const int n0 = blockIdx.x * 32;
    const int wid = threadIdx.x >> 5, l = threadIdx.x & 31;
    const float al = alpha_p[0];
    const float* wr = Wr + sidx * 256;

    #pragma unroll
    for (int i = 0; i < 4; i++) {
        int nl = wid * 4 + i;
        int node = n0 + nl;
        if (node < M) {
            size_t base = (size_t)node * 256;
            float h[8]; float sum = 0.f, sq = 0.f;
            #pragma unroll
            for (int j = 0; j < 8; j++) {
                int idx = j * 32 + l;
                float v = al * (g_Rn[base + idx] + g_Gn[base + idx]) + (1.f - al) * g_R[base + idx];
                h[j] = v; sum += v; sq += v * v;
            }
            #pragma unroll
            for (int o = 16; o > 0; o >>= 1) {
                sum += __shfl_xor_sync(0xffffffffu, sum, o);
                sq  += __shfl_xor_sync(0xffffffffu, sq, o);
            }
            float mu  = sum * (1.f / 256.f);
            float var = sq * (1.f / 256.f) - mu * mu;
            float rstd = rsqrtf(var + 1e-5f);
            float dot = 0.f;
            #pragma unroll
            for (int j = 0; j < 8; j++) {
                int idx = j * 32 + l;
                float y = (h[j] - mu) * rstd * gamma[idx] + beta[idx];
                g_R[base + idx] = y;
                bf16 yh = __float2bfloat16(y);
                bf16 yl = __float2bfloat16(y - __bfloat162float(yh));
                g_Rh[base + idx] = yh;
                g_Rl[base + idx] = yl;
                sh[nl][idx] = yh;
                sl[nl][idx] = yl;
                dot += y * wr[idx];
            }
            #pragma unroll
            for (int o = 16; o > 0; o >>= 1) dot += __shfl_xor_sync(0xffffffffu, dot, o);
            if (l == 0) out[node] += wgt[sidx] * (dot + br[sidx]);
        }
    }

    if (writeRT) {
        __syncthreads();
        int d = threadIdx.x;
        size_t Nn = (size_t)M;
        if (n0 + 32 <= M && ((Nn * 2) & 15) == 0) {
            uint32_t ph[16], pl[16];
            #pragma unroll
            for (int p = 0; p < 16; p++) {
                uint32_t h0 = __bfloat16_as_ushort(sh[p * 2][d]);
                uint32_t h1 = __bfloat16_as_ushort(sh[p * 2 + 1][d]);
                uint32_t l0 = __bfloat16_as_ushort(sl[p * 2][d]);
                uint32_t l1 = __bfloat16_as_ushort(sl[p * 2 + 1][d]);
                ph[p] = h0 | (h1 << 16);
                pl[p] = l0 | (l1 << 16);
            }
            size_t gb = (size_t)d * Nn + n0;
            #pragma unroll
            for (int q = 0; q < 4; q++) {
                *(int4*)&g_RTh[gb + q * 8] = *(int4*)&ph[q * 4];
                *(int4*)&g_RTl[gb + q * 8] = *(int4*)&pl[q * 4];
            }
        } else {
            for (int nl = 0; nl < 32; nl++) {
                if (n0 + nl < M) {
                    g_RTh[(size_t)d * Nn + n0 + nl] = sh[nl][d];
                    g_RTl[(size_t)d * Nn + n0 + nl] = sl[nl][d];
                }
            }
        }
    }
}

__global__ void readout0(const float* __restrict__ Wr, const float* __restrict__ br,
                         const float* __restrict__ wgt, float* __restrict__ out, int M)
{
    int gw = (blockIdx.x * blockDim.x + threadIdx.x) >> 5;
    int l = threadIdx.x & 31;
    if (gw >= M) return;
    float dot = 0.f;
    #pragma unroll
    for (int j = 0; j < 8; j++) {
        int idx = j * 32 + l;
        dot += g_R[(size_t)gw * 256 + idx] * Wr[idx];
    }
    #pragma unroll
    for (int o = 16; o > 0; o >>= 1) dot += __shfl_xor_sync(0xffffffffu, dot, o);
    if (l == 0) out[gw] = wgt[0] * (dot + br[0]);
}

// ---------------- host orchestration ------------------------------------------
extern "C" void kernel_launch(void* const* d_in, const int* in_sizes, int n_in,
                              void* d_out, int out_size)
{
    const float* x     = (const float*)d_in[0];
    const int*   ei    = (const int*)  d_in[1];
    const float* W1    = (const float*)d_in[2];
    const float* b1    = (const float*)d_in[3];
    const float* Wq    = (const float*)d_in[4];
    const float* bq    = (const float*)d_in[5];
    const float* Wk    = (const float*)d_in[6];
    const float* bk    = (const float*)d_in[7];
    const float* gamma = (const float*)d_in[8];
    const float* beta  = (const float*)d_in[9];
    const float* alpha = (const float*)d_in[10];
    const float* Wr    = (const float*)d_in[11];
    const float* br    = (const float*)d_in[12];
    const float* wgt   = (const float*)d_in[13];
    float* out = (float*)d_out;

    const int N = in_sizes[0] / FIN;
    const int E = in_sizes[1] / 2;
    const int* erow = ei;
    const int* ecol = ei + E;

    static cudaStream_t sB = 0;
    static cudaEvent_t evFork = 0, evA0 = 0, evG[3], evL[2];
    static bool init_done = false;
    if (!init_done) {
        cudaFuncSetAttribute(mma_gemm<0>, cudaFuncAttributeMaxDynamicSharedMemorySize, 2 * STAGE_BYTES);
        cudaFuncSetAttribute(mma_gemm<1>, cudaFuncAttributeMaxDynamicSharedMemorySize, 2 * STAGE_BYTES);
        cudaFuncSetAttribute(mma_gemm<2>, cudaFuncAttributeMaxDynamicSharedMemorySize, 2 * STAGE_BYTES);
        cudaStreamCreateWithFlags(&sB, cudaStreamNonBlocking);
        cudaEventCreateWithFlags(&evFork, cudaEventDisableTiming);
        cudaEventCreateWithFlags(&evA0, cudaEventDisableTiming);
        for (int i = 0; i < 3; i++) cudaEventCreateWithFlags(&evG[i], cudaEventDisableTiming);
        for (int i = 0; i < 2; i++) cudaEventCreateWithFlags(&evL[i], cudaEventDisableTiming);
        init_done = true;
    }

    static float *pR = 0, *pRn = 0, *pKv = 0, *pStats = 0;
    static bf16 *pRh = 0, *pRl = 0, *pRTh = 0, *pRTl = 0, *pkTh = 0, *pkTl = 0,
                *pqkh = 0, *pqkl = 0, *pWTh = 0, *pWTl = 0, *pkvTh = 0, *pkvTl = 0;
    if (!pR) {
        cudaGetSymbolAddress((void**)&pR,    g_R);
        cudaGetSymbolAddress((void**)&pRn,   g_Rn);
        cudaGetSymbolAddress((void**)&pKv,   g_kv);
        cudaGetSymbolAddress((void**)&pStats,g_stats);
        cudaGetSymbolAddress((void**)&pRh,   g_Rh);
        cudaGetSymbolAddress((void**)&pRl,   g_Rl);
        cudaGetSymbolAddress((void**)&pRTh,  g_RTh);
        cudaGetSymbolAddress((void**)&pRTl,  g_RTl);
        cudaGetSymbolAddress((void**)&pkTh,  g_kTh);
        cudaGetSymbolAddress((void**)&pkTl,  g_kTl);
        cudaGetSymbolAddress((void**)&pqkh,  g_qkh);
        cudaGetSymbolAddress((void**)&pqkl,  g_qkl);
        cudaGetSymbolAddress((void**)&pWTh,  g_WqkTh);
        cudaGetSymbolAddress((void**)&pWTl,  g_WqkTl);
        cudaGetSymbolAddress((void**)&pkvTh, g_kvTh);
        cudaGetSymbolAddress((void**)&pkvTl, g_kvTl);
    }

    const int mtiles = (N + 127) / 128;
    const int tgrid = (N * 32 + 255) / 256;
    const int nb1 = (N + 1023) / 1024;

    // ---- fork stream B into the capture, run CSR build there ----
    cudaEventRecord(evFork, 0);
    cudaStreamWaitEvent(sB, evFork, 0);

    zero_i2     <<<(N + 255) / 256, 256, 0, sB>>>(N);
    cnt_deg     <<<(E + 255) / 256, 256, 0, sB>>>(ecol, E);
    invsqrt_k   <<<(N + 255) / 256, 256, 0, sB>>>(N);
    scan1       <<<nb1, 256, 0, sB>>>(N);
    scan2       <<<1, 128, 0, sB>>>(nb1);
    scan3       <<<(N + 255) / 256, 256, 0, sB>>>(N, E);
    edge_scatter<<<(E + 255) / 256, 256, 0, sB>>>(erow, ecol, E);

    // ---- stream A: weights + input GEMM ----
    build_wqkT<<<(2 * H * H + 255) / 256, 256>>>(Wq, Wk);
    {
        dim3 g((H + 127) / 128, (N + 127) / 128);
        sgemm_relu<<<g, 256>>>(x, FIN, W1, H, b1, pR, H, N, FIN, pRh, pRl);
    }
    cudaEventRecord(evA0, 0);              // Rh ready for gather iteration 0
    readout0<<<tgrid, 256>>>(Wr, br, wgt, out, N);
    {
        dim3 g((N + 31) / 32, 8), b(32, 8);
        transpose2_bf16<<<g, b>>>(pRh, pRl, pRTh, pRTl, N, 256, N);
    }

    cudaStreamWaitEvent(sB, evA0, 0);

    for (int it = 0; it < 3; it++) {
        // stream B: gather into Gn (concurrent with attention chain)
        if (it > 0) cudaStreamWaitEvent(sB, evL[it - 1], 0);
        gcn_gather_bf16<<<(N + 7) / 8, 256, 0, sB>>>(N);
        cudaEventRecord(evG[it], sB);

        // stream A: attention chain
        zero_k<<<(H * H + 255) / 256, 256>>>(pKv, H * H);
        zero_k<<<3, 256>>>(pStats, 2 + 2 * H);

        mma_gemm<0><<<dim3(8, mtiles, 1), 256, 2 * STAGE_BYTES>>>(
            pRh, pRl, 256, pWTh, pWTl, 256, N, 256, 256,
            bq, bk, nullptr, pqkh, pqkl, pkTh, pkTl);

        vsum_k<<<(N + 127) / 128, 256>>>(N);

        {
            int zchunks = (N + 1023) / 1024;
            mma_gemm<2><<<dim3(4, 2, zchunks), 256, 2 * STAGE_BYTES>>>(
                pkTh, pkTl, N, pRTh, pRTl, N, 256, N, 1024,
                nullptr, nullptr, nullptr, nullptr, nullptr, nullptr, nullptr);
        }

        finalize_s<<<1, 1>>>();
        den_kernel<<<tgrid, 256>>>(N, (float)N);
        build_kvT<<<(H * H + 255) / 256, 256>>>();

        mma_gemm<1><<<dim3(4, mtiles, 1), 256, 2 * STAGE_BYTES>>>(
            pqkh, pqkl, 512, pkvTh, pkvTl, 256, N, 256, 256,
            nullptr, nullptr, pRn, nullptr, nullptr, nullptr, nullptr);

        // join gather, then blend + LN
        cudaStreamWaitEvent(0, evG[it], 0);
        blend_ln<<<(N + 31) / 32, 256>>>(alpha, gamma, beta, Wr, br, wgt,
                                         it + 1, out, N, it < 2 ? 1 : 0);
        if (it < 2) cudaEventRecord(evL[it], 0);   // R/Rh updated for next gather
    }
}